// round 13
// baseline (speedup 1.0000x reference)
#include <cuda_runtime.h>
#include <cuda_fp16.h>
#include <cstdint>

#define P_    8
#define T_    2048
#define N_    8192
#define M_    20000
#define DLAT  1024
#define DFEAT 512
#define DIN   1536
#define MSPLIT 20
#define MCHUNK 1000
#define NSCH  8
#define SCHSZ 1024

// ---- GEMM config (round-5 proven shape) ----
#define BM 128
#define BN 128
#define BK 64
#define NSTG 3
#define STG_BYTES 32768                // A 16K + B 16K
#define GEMM_SMEM (NSTG * STG_BYTES)   // 96KB

// ---------------- scratch ----------------
__device__ float g_part_d[N_ * MSPLIT];
__device__ int   g_part_i[N_ * MSPLIT];
__device__ int   g_nearest[N_];
__device__ float g_mp_d[2 * P_ * NSCH * T_];
__device__ int   g_mp_i[2 * P_ * NSCH * T_];
__device__ int   g_fidx[2 * P_ * T_];            // [which][p][t] -> precomputed_feats row
__device__ __half g_A[2L * P_ * T_ * DIN];       // [z][m][k] fp16, K=1536
__device__ __half g_B[2L * DLAT * DIN];          // W^T fp16 [z][n][k]

// ---------------- helpers ----------------
__device__ __forceinline__ uint32_t smem_u32(const void* p) {
    uint32_t a;
    asm("{ .reg .u64 t; cvta.to.shared.u64 t, %1; cvt.u32.u64 %0, t; }" : "=r"(a) : "l"(p));
    return a;
}
__device__ __forceinline__ void cp16(uint32_t dst, const void* src) {
    asm volatile("cp.async.cg.shared.global [%0], [%1], 16;" :: "r"(dst), "l"(src) : "memory");
}
#define CP_COMMIT() asm volatile("cp.async.commit_group;" ::: "memory")
#define CP_WAIT1()  asm volatile("cp.async.wait_group 1;" ::: "memory")

__device__ __forceinline__ void ldmx4(uint32_t addr, uint32_t& r0, uint32_t& r1,
                                      uint32_t& r2, uint32_t& r3) {
    asm volatile("ldmatrix.sync.aligned.m8n8.x4.shared.b16 {%0,%1,%2,%3}, [%4];"
                 : "=r"(r0), "=r"(r1), "=r"(r2), "=r"(r3) : "r"(addr));
}
__device__ __forceinline__ void mma16816(float& c0, float& c1, float& c2, float& c3,
                                         uint32_t a0, uint32_t a1, uint32_t a2, uint32_t a3,
                                         uint32_t b0, uint32_t b1) {
    asm volatile("mma.sync.aligned.m16n8k16.row.col.f32.f16.f16.f32 "
                 "{%0,%1,%2,%3}, {%4,%5,%6,%7}, {%8,%9}, {%0,%1,%2,%3};"
                 : "+f"(c0), "+f"(c1), "+f"(c2), "+f"(c3)
                 : "r"(a0), "r"(a1), "r"(a2), "r"(a3), "r"(b0), "r"(b1));
}
__device__ __forceinline__ uint32_t swz(int row, int kg) {
    return (uint32_t)(row * 128 + ((kg ^ (row & 7)) << 4));
}
__device__ __forceinline__ uint2 pack4h(float4 v) {
    __half hx = __float2half_rn(v.x), hy = __float2half_rn(v.y);
    __half hz = __float2half_rn(v.z), hw = __float2half_rn(v.w);
    uint2 r;
    r.x = ((uint32_t)*(uint16_t*)&hy << 16) | (uint32_t)*(uint16_t*)&hx;
    r.y = ((uint32_t)*(uint16_t*)&hw << 16) | (uint32_t)*(uint16_t*)&hz;
    return r;
}

// ---------------- kernel 1: obj_pts[0] vs precomputed_points ----------------
// grid (N/1024, MSPLIT), block 256, 4 q/thread, 1000-candidate chunks
__global__ void nn1_partial(const float* __restrict__ os, const float* __restrict__ pts) {
    __shared__ float4 sP[MCHUNK];
    const int ms = blockIdx.y;
    const int m0 = ms * MCHUNK;
    for (int i = threadIdx.x; i < MCHUNK; i += 256) {
        float x = pts[(size_t)(m0 + i) * 3 + 0];
        float y = pts[(size_t)(m0 + i) * 3 + 1];
        float z = pts[(size_t)(m0 + i) * 3 + 2];
        sP[i] = make_float4(x, y, z, x * x + y * y + z * z);
    }
    __syncthreads();
    float qx[4], qy[4], qz[4], best[4];
    int bi[4];
    #pragma unroll
    for (int u = 0; u < 4; u++) {
        const int q = blockIdx.x * 1024 + u * 256 + threadIdx.x;
        qx[u] = -2.0f * os[(size_t)q * 6 + 0];
        qy[u] = -2.0f * os[(size_t)q * 6 + 1];
        qz[u] = -2.0f * os[(size_t)q * 6 + 2];
        best[u] = 3.4e38f;
        bi[u] = 0;
    }
    #pragma unroll 4
    for (int i = 0; i < MCHUNK; i++) {
        float4 c = sP[i];
        #pragma unroll
        for (int u = 0; u < 4; u++) {
            float d = fmaf(qx[u], c.x, fmaf(qy[u], c.y, fmaf(qz[u], c.z, c.w)));
            if (d < best[u]) { best[u] = d; bi[u] = i; }
        }
    }
    #pragma unroll
    for (int u = 0; u < 4; u++) {
        const int q = blockIdx.x * 1024 + u * 256 + threadIdx.x;
        g_part_d[q * MSPLIT + ms] = best[u];
        g_part_i[q * MSPLIT + ms] = m0 + bi[u];
    }
}

__global__ void nn1_reduce() {
    const int q = blockIdx.x * blockDim.x + threadIdx.x;
    float best = g_part_d[q * MSPLIT];
    int bi = g_part_i[q * MSPLIT];
    #pragma unroll
    for (int s = 1; s < MSPLIT; s++) {
        float d = g_part_d[q * MSPLIT + s];
        if (d < best) { best = d; bi = g_part_i[q * MSPLIT + s]; }
    }
    g_nearest[q] = bi;
}

// ---------------- kernel 2: match partial + reduce (reduce does nearest lookup) ----------------
__global__ void match_partial(const float* __restrict__ os,
                              const float* __restrict__ local_pc,
                              const float* __restrict__ global_pc) {
    __shared__ float4 sP[SCHSZ];
    const int p = blockIdx.y;
    const int which = blockIdx.z >> 3;
    const int ch = blockIdx.z & 7;
    const int nt = ch * SCHSZ;
    const float* qsrc = (which == 0) ? local_pc : global_pc;
    const int tb = blockIdx.x * 1024 + threadIdx.x;

    for (int i = threadIdx.x; i < SCHSZ; i += 256) {
        size_t bsrc = ((size_t)p * N_ + nt + i) * 6;
        float x = os[bsrc + 0], y = os[bsrc + 1], z = os[bsrc + 2];
        sP[i] = make_float4(x, y, z, x * x + y * y + z * z);
    }

    float qx[4], qy[4], qz[4], best[4];
    int bi[4];
    #pragma unroll
    for (int u = 0; u < 4; u++) {
        const size_t qb = ((size_t)p * T_ + tb + u * 256) * 3;
        qx[u] = -2.0f * qsrc[qb + 0];
        qy[u] = -2.0f * qsrc[qb + 1];
        qz[u] = -2.0f * qsrc[qb + 2];
        best[u] = 3.4e38f;
        bi[u] = 0;
    }
    __syncthreads();
    #pragma unroll 4
    for (int i = 0; i < SCHSZ; i++) {
        float4 c = sP[i];
        #pragma unroll
        for (int u = 0; u < 4; u++) {
            float d = fmaf(qx[u], c.x, fmaf(qy[u], c.y, fmaf(qz[u], c.z, c.w)));
            if (d < best[u]) { best[u] = d; bi[u] = nt + i; }
        }
    }
    #pragma unroll
    for (int u = 0; u < 4; u++) {
        size_t o = (((size_t)which * P_ + p) * NSCH + ch) * T_ + tb + u * 256;
        g_mp_d[o] = best[u];
        g_mp_i[o] = bi[u];
    }
}

__global__ void match_reduce() {
    const int g = blockIdx.x * 256 + threadIdx.x;
    const int wp = g / T_;
    const int t = g % T_;
    size_t base = ((size_t)wp * NSCH) * T_ + t;
    float best = g_mp_d[base];
    int bi = g_mp_i[base];
    #pragma unroll
    for (int c = 1; c < NSCH; c++) {
        float d = g_mp_d[base + (size_t)c * T_];
        if (d < best) { best = d; bi = g_mp_i[base + (size_t)c * T_]; }
    }
    g_fidx[g] = g_nearest[bi];
}

// ---------------- conversions ----------------
// raw fp32 -> fp16 A[k<1024]; grid (16384, 2), 256 thr
__global__ void convA(const float* __restrict__ geo_raw, const float* __restrict__ obj_raw) {
    const int z = blockIdx.y;
    const int m = blockIdx.x;
    const float* src = (z ? obj_raw : geo_raw) + (size_t)m * DLAT + threadIdx.x * 4;
    float4 v = *(const float4*)src;
    size_t base = ((size_t)z * (P_ * T_) + m) * DIN + threadIdx.x * 4;
    *(uint2*)(g_A + base) = pack4h(v);
}

// gather + convert feats -> fp16 A[k>=1024]; grid 32768, 128 thr
__global__ void gather_conv(const float* __restrict__ pf) {
    const int row = blockIdx.x;
    const int fi = g_fidx[row];
    float4 v = *(const float4*)(pf + (size_t)fi * DFEAT + threadIdx.x * 4);
    size_t base = (size_t)row * DIN + DLAT + threadIdx.x * 4;
    *(uint2*)(g_A + base) = pack4h(v);
}

// W transpose -> fp16 [n][k] K=1536
__global__ void convW(const float* __restrict__ Wg, const float* __restrict__ Wo) {
    __shared__ float tile[32][33];
    const int g = blockIdx.z;
    const float* W = g ? Wo : Wg;
    const int kb = blockIdx.x * 32, nb = blockIdx.y * 32;
    for (int i = threadIdx.y; i < 32; i += 8)
        tile[i][threadIdx.x] = W[(size_t)(kb + i) * DLAT + nb + threadIdx.x];
    __syncthreads();
    for (int i = threadIdx.y; i < 32; i += 8) {
        float v = tile[threadIdx.x][i];
        size_t idx = (size_t)g * DLAT * DIN + (size_t)(nb + i) * DIN + kb + threadIdx.x;
        g_B[idx] = __float2half_rn(v);
    }
}

// ---------------- single fp16 mma.sync GEMM, K=1536, bias epilogue ----------------
extern __shared__ char dynsmem[];

__device__ __forceinline__ void load_chunk(uint32_t sbase, int stage, int kglob,
                                           const __half* A, const __half* B,
                                           int m0, int n0, int tid) {
    const uint32_t st = sbase + stage * STG_BYTES;
    #pragma unroll
    for (int p = 0; p < 4; p++) {
        int lin = p * 256 + tid;
        int row = lin >> 3, kg = lin & 7;
        cp16(st + swz(row, kg), A + (size_t)(m0 + row) * DIN + kglob + kg * 8);
    }
    #pragma unroll
    for (int p = 0; p < 4; p++) {
        int lin = p * 256 + tid;
        int row = lin >> 3, kg = lin & 7;
        cp16(st + 16384 + swz(row, kg), B + (size_t)(n0 + row) * DIN + kglob + kg * 8);
    }
}

__global__ void __launch_bounds__(256, 2)
gemm_mma(const float* __restrict__ bg, const float* __restrict__ bo,
         float* __restrict__ out) {
    const int z = blockIdx.z;
    const int n0 = blockIdx.x * BN;
    const int m0 = blockIdx.y * BM;
    const int tid = threadIdx.x;
    const int wid = tid >> 5;
    const int lane = tid & 31;
    const int wm = wid & 1;
    const int wn = wid >> 1;

    const __half* A = g_A + (size_t)z * (P_ * T_) * DIN;
    const __half* B = g_B + (size_t)z * DLAT * DIN;
    float* C = out + (size_t)z * (P_ * T_) * DLAT;
    const float* bias = z ? bo : bg;

    const uint32_t sbase = smem_u32(dynsmem);

    float acc[4][4][4];
    #pragma unroll
    for (int i = 0; i < 4; i++)
        #pragma unroll
        for (int j = 0; j < 4; j++)
            #pragma unroll
            for (int r = 0; r < 4; r++) acc[i][j][r] = 0.0f;

    const int a_rb = wm * 64 + (lane & 15);
    const int a_gs = lane >> 4;
    const int b_rb = wn * 32 + (lane & 7) + ((lane & 16) >> 1);
    const int b_gs = (lane >> 3) & 1;

    load_chunk(sbase, 0, 0, A, B, m0, n0, tid); CP_COMMIT();
    load_chunk(sbase, 1, BK, A, B, m0, n0, tid); CP_COMMIT();

    const int NCH = DIN / BK;   // 24
    for (int kc = 0; kc < NCH; kc++) {
        CP_WAIT1();
        __syncthreads();
        if (kc + 2 < NCH)
            load_chunk(sbase, (kc + 2) % NSTG, (kc + 2) * BK, A, B, m0, n0, tid);
        CP_COMMIT();

        const uint32_t sA = sbase + (kc % NSTG) * STG_BYTES;
        const uint32_t sB = sA + 16384;
        #pragma unroll
        for (int k4 = 0; k4 < 4; k4++) {
            uint32_t a[4][4];
            #pragma unroll
            for (int mi = 0; mi < 4; mi++)
                ldmx4(sA + swz(a_rb + mi * 16, k4 * 2 + a_gs),
                      a[mi][0], a[mi][1], a[mi][2], a[mi][3]);
            #pragma unroll
            for (int npp = 0; npp < 2; npp++) {
                uint32_t b0, b1, b2, b3;
                ldmx4(sB + swz(b_rb + npp * 16, k4 * 2 + b_gs), b0, b1, b2, b3);
                #pragma unroll
                for (int mi = 0; mi < 4; mi++) {
                    mma16816(acc[mi][npp*2][0], acc[mi][npp*2][1], acc[mi][npp*2][2], acc[mi][npp*2][3],
                             a[mi][0], a[mi][1], a[mi][2], a[mi][3], b0, b1);
                    mma16816(acc[mi][npp*2+1][0], acc[mi][npp*2+1][1], acc[mi][npp*2+1][2], acc[mi][npp*2+1][3],
                             a[mi][0], a[mi][1], a[mi][2], a[mi][3], b2, b3);
                }
            }
        }
    }

    // epilogue: bias + store
    const int row_in = lane >> 2;
    const int col_in = (lane & 3) * 2;
    #pragma unroll
    for (int np = 0; np < 4; np++) {
        const int col = n0 + wn * 32 + np * 8 + col_in;
        const float bx = __ldg(bias + col);
        const float by = __ldg(bias + col + 1);
        #pragma unroll
        for (int mi = 0; mi < 4; mi++) {
            const int r0 = m0 + wm * 64 + mi * 16 + row_in;
            *(float2*)(C + (size_t)r0 * DLAT + col) =
                make_float2(acc[mi][np][0] + bx, acc[mi][np][1] + by);
            *(float2*)(C + (size_t)(r0 + 8) * DLAT + col) =
                make_float2(acc[mi][np][2] + bx, acc[mi][np][3] + by);
        }
    }
}

// ---------------- launch ----------------
extern "C" void kernel_launch(void* const* d_in, const int* in_sizes, int n_in,
                              void* d_out, int out_size) {
    const float* object_surface = (const float*)d_in[0];
    const float* pre_pts        = (const float*)d_in[1];
    const float* pre_feats      = (const float*)d_in[2];
    const float* geo_raw        = (const float*)d_in[3];
    const float* obj_raw        = (const float*)d_in[4];
    const float* local_pc       = (const float*)d_in[5];
    const float* global_pc      = (const float*)d_in[6];
    const float* Wg             = (const float*)d_in[7];
    const float* bg             = (const float*)d_in[8];
    const float* Wo             = (const float*)d_in[9];
    const float* bo             = (const float*)d_in[10];
    float* out = (float*)d_out;

    static cudaStream_t s2 = nullptr;
    static cudaEvent_t evFork = nullptr, evS2 = nullptr;
    static bool inited = false;
    if (!inited) {
        cudaFuncSetAttribute(gemm_mma, cudaFuncAttributeMaxDynamicSharedMemorySize, GEMM_SMEM);
        cudaStreamCreateWithFlags(&s2, cudaStreamNonBlocking);
        cudaEventCreateWithFlags(&evFork, cudaEventDisableTiming);
        cudaEventCreateWithFlags(&evS2, cudaEventDisableTiming);
        inited = true;
    }

    // fork: full NN chain + gather on s2
    cudaEventRecord(evFork, 0);
    cudaStreamWaitEvent(s2, evFork, 0);

    nn1_partial<<<dim3(N_ / 1024, MSPLIT), 256, 0, s2>>>(object_surface, pre_pts);
    nn1_reduce<<<N_ / 256, 256, 0, s2>>>();
    match_partial<<<dim3(T_ / 1024, P_, 2 * NSCH), 256, 0, s2>>>(object_surface, local_pc, global_pc);
    match_reduce<<<2 * P_ * T_ / 256, 256, 0, s2>>>();
    gather_conv<<<2 * P_ * T_, DFEAT / 4, 0, s2>>>(pre_feats);
    cudaEventRecord(evS2, s2);

    // s1: conversions (concurrent with s2 chain)
    convW<<<dim3(DIN / 32, DLAT / 32, 2), dim3(32, 8)>>>(Wg, Wo);
    convA<<<dim3(P_ * T_, 2), 256>>>(geo_raw, obj_raw);

    // join: single K=1536 GEMM with bias epilogue
    cudaStreamWaitEvent(0, evS2, 0);
    gemm_mma<<<dim3(DLAT / BN, (P_ * T_) / BM, 2), 256, GEMM_SMEM>>>(bg, bo, out);
}

// round 14
// speedup vs baseline: 1.0354x; 1.0354x over previous
#include <cuda_runtime.h>
#include <cuda_fp16.h>
#include <cstdint>

#define P_    8
#define T_    2048
#define N_    8192
#define M_    20000
#define DLAT  1024
#define DFEAT 512
#define DIN   1536
#define MSPLIT 20
#define MCHUNK 1000
#define NSCH  8
#define SCHSZ 1024

// ---- GEMM config (round-5/8/12 proven shape) ----
#define BM 128
#define BN 128
#define BK 64
#define NSTG 3
#define STG_BYTES 32768                // A 16K + B 16K
#define GEMM_SMEM (NSTG * STG_BYTES)   // 96KB

// ---------------- scratch ----------------
__device__ float g_part_d[N_ * MSPLIT];
__device__ int   g_part_i[N_ * MSPLIT];
__device__ int   g_nearest[N_];
__device__ float g_mp_d[2 * P_ * NSCH * T_];
__device__ int   g_mp_i[2 * P_ * NSCH * T_];
__device__ int   g_match2[2 * P_ * T_];          // [which][p][t] -> obj-point idx
__device__ __half g_A[2L * P_ * T_ * DLAT];      // [z][m][k<1024] fp16
__device__ __half g_PF[(size_t)N_ * DFEAT];      // fp16 feats per obj point
__device__ __half g_B1[2L * DLAT * DLAT];        // W[:1024]^T fp16 [z][n][k]
__device__ __half g_B2[2L * DLAT * DFEAT];       // W[1024:]^T fp16 [z][n][k]
__device__ float g_pf2u[2L * N_ * DLAT];         // fp32 pf @ W2 per obj point

// ---------------- helpers ----------------
__device__ __forceinline__ uint32_t smem_u32(const void* p) {
    uint32_t a;
    asm("{ .reg .u64 t; cvta.to.shared.u64 t, %1; cvt.u32.u64 %0, t; }" : "=r"(a) : "l"(p));
    return a;
}
__device__ __forceinline__ void cp16(uint32_t dst, const void* src) {
    asm volatile("cp.async.cg.shared.global [%0], [%1], 16;" :: "r"(dst), "l"(src) : "memory");
}
#define CP_COMMIT() asm volatile("cp.async.commit_group;" ::: "memory")
#define CP_WAIT1()  asm volatile("cp.async.wait_group 1;" ::: "memory")

__device__ __forceinline__ void ldmx4(uint32_t addr, uint32_t& r0, uint32_t& r1,
                                      uint32_t& r2, uint32_t& r3) {
    asm volatile("ldmatrix.sync.aligned.m8n8.x4.shared.b16 {%0,%1,%2,%3}, [%4];"
                 : "=r"(r0), "=r"(r1), "=r"(r2), "=r"(r3) : "r"(addr));
}
__device__ __forceinline__ void mma16816(float& c0, float& c1, float& c2, float& c3,
                                         uint32_t a0, uint32_t a1, uint32_t a2, uint32_t a3,
                                         uint32_t b0, uint32_t b1) {
    asm volatile("mma.sync.aligned.m16n8k16.row.col.f32.f16.f16.f32 "
                 "{%0,%1,%2,%3}, {%4,%5,%6,%7}, {%8,%9}, {%0,%1,%2,%3};"
                 : "+f"(c0), "+f"(c1), "+f"(c2), "+f"(c3)
                 : "r"(a0), "r"(a1), "r"(a2), "r"(a3), "r"(b0), "r"(b1));
}
__device__ __forceinline__ uint32_t swz(int row, int kg) {
    return (uint32_t)(row * 128 + ((kg ^ (row & 7)) << 4));
}
__device__ __forceinline__ uint2 pack4h(float4 v) {
    __half hx = __float2half_rn(v.x), hy = __float2half_rn(v.y);
    __half hz = __float2half_rn(v.z), hw = __float2half_rn(v.w);
    uint2 r;
    r.x = ((uint32_t)*(uint16_t*)&hy << 16) | (uint32_t)*(uint16_t*)&hx;
    r.y = ((uint32_t)*(uint16_t*)&hw << 16) | (uint32_t)*(uint16_t*)&hz;
    return r;
}

// ---------------- kernel 1: obj_pts[0] vs precomputed_points ----------------
// grid (N/1024, MSPLIT), block 256, 4 q/thread, 1000-candidate chunks
__global__ void nn1_partial(const float* __restrict__ os, const float* __restrict__ pts) {
    __shared__ float4 sP[MCHUNK];
    const int ms = blockIdx.y;
    const int m0 = ms * MCHUNK;
    for (int i = threadIdx.x; i < MCHUNK; i += 256) {
        float x = pts[(size_t)(m0 + i) * 3 + 0];
        float y = pts[(size_t)(m0 + i) * 3 + 1];
        float z = pts[(size_t)(m0 + i) * 3 + 2];
        sP[i] = make_float4(x, y, z, x * x + y * y + z * z);
    }
    __syncthreads();
    float qx[4], qy[4], qz[4], best[4];
    int bi[4];
    #pragma unroll
    for (int u = 0; u < 4; u++) {
        const int q = blockIdx.x * 1024 + u * 256 + threadIdx.x;
        qx[u] = -2.0f * os[(size_t)q * 6 + 0];
        qy[u] = -2.0f * os[(size_t)q * 6 + 1];
        qz[u] = -2.0f * os[(size_t)q * 6 + 2];
        best[u] = 3.4e38f;
        bi[u] = 0;
    }
    #pragma unroll 4
    for (int i = 0; i < MCHUNK; i++) {
        float4 c = sP[i];
        #pragma unroll
        for (int u = 0; u < 4; u++) {
            float d = fmaf(qx[u], c.x, fmaf(qy[u], c.y, fmaf(qz[u], c.z, c.w)));
            if (d < best[u]) { best[u] = d; bi[u] = i; }
        }
    }
    #pragma unroll
    for (int u = 0; u < 4; u++) {
        const int q = blockIdx.x * 1024 + u * 256 + threadIdx.x;
        g_part_d[q * MSPLIT + ms] = best[u];
        g_part_i[q * MSPLIT + ms] = m0 + bi[u];
    }
}

__global__ void nn1_reduce() {
    const int q = blockIdx.x * blockDim.x + threadIdx.x;
    float best = g_part_d[q * MSPLIT];
    int bi = g_part_i[q * MSPLIT];
    #pragma unroll
    for (int s = 1; s < MSPLIT; s++) {
        float d = g_part_d[q * MSPLIT + s];
        if (d < best) { best = d; bi = g_part_i[q * MSPLIT + s]; }
    }
    g_nearest[q] = bi;
}

// ---------------- kernel 2: match partial (8 q/thread, 1024-cand chunk) ----------------
// grid (1, P, 2*NSCH), block 256 — one block covers all T=2048 queries of (p, chunk)
__global__ void match_partial(const float* __restrict__ os,
                              const float* __restrict__ local_pc,
                              const float* __restrict__ global_pc) {
    __shared__ float4 sP[SCHSZ];
    const int p = blockIdx.y;
    const int which = blockIdx.z >> 3;
    const int ch = blockIdx.z & 7;
    const int nt = ch * SCHSZ;
    const float* qsrc = (which == 0) ? local_pc : global_pc;

    for (int i = threadIdx.x; i < SCHSZ; i += 256) {
        size_t bsrc = ((size_t)p * N_ + nt + i) * 6;
        float x = os[bsrc + 0], y = os[bsrc + 1], z = os[bsrc + 2];
        sP[i] = make_float4(x, y, z, x * x + y * y + z * z);
    }

    float qx[8], qy[8], qz[8], best[8];
    int bi[8];
    #pragma unroll
    for (int u = 0; u < 8; u++) {
        const size_t qb = ((size_t)p * T_ + u * 256 + threadIdx.x) * 3;
        qx[u] = -2.0f * qsrc[qb + 0];
        qy[u] = -2.0f * qsrc[qb + 1];
        qz[u] = -2.0f * qsrc[qb + 2];
        best[u] = 3.4e38f;
        bi[u] = 0;
    }
    __syncthreads();
    #pragma unroll 2
    for (int i = 0; i < SCHSZ; i++) {
        float4 c = sP[i];
        #pragma unroll
        for (int u = 0; u < 8; u++) {
            float d = fmaf(qx[u], c.x, fmaf(qy[u], c.y, fmaf(qz[u], c.z, c.w)));
            if (d < best[u]) { best[u] = d; bi[u] = nt + i; }
        }
    }
    #pragma unroll
    for (int u = 0; u < 8; u++) {
        size_t o = (((size_t)which * P_ + p) * NSCH + ch) * T_ + u * 256 + threadIdx.x;
        g_mp_d[o] = best[u];
        g_mp_i[o] = bi[u];
    }
}

__global__ void match_reduce() {
    const int g = blockIdx.x * 256 + threadIdx.x;
    const int wp = g / T_;
    const int t = g % T_;
    size_t base = ((size_t)wp * NSCH) * T_ + t;
    float best = g_mp_d[base];
    int bi = g_mp_i[base];
    #pragma unroll
    for (int c = 1; c < NSCH; c++) {
        float d = g_mp_d[base + (size_t)c * T_];
        if (d < best) { best = d; bi = g_mp_i[base + (size_t)c * T_]; }
    }
    g_match2[g] = bi;
}

// ---------------- conversions ----------------
__global__ void convA(const float* __restrict__ geo_raw, const float* __restrict__ obj_raw) {
    const int z = blockIdx.y;
    const int m = blockIdx.x;
    const float* src = (z ? obj_raw : geo_raw) + (size_t)m * DLAT + threadIdx.x * 4;
    float4 v = *(const float4*)src;
    size_t base = ((size_t)z * (P_ * T_) + m) * DLAT + threadIdx.x * 4;
    *(uint2*)(g_A + base) = pack4h(v);
}

__global__ void gatherPF(const float* __restrict__ pf) {
    const int q = blockIdx.x;
    const int fi = g_nearest[q];
    float4 v = *(const float4*)(pf + (size_t)fi * DFEAT + threadIdx.x * 4);
    *(uint2*)(g_PF + (size_t)q * DFEAT + threadIdx.x * 4) = pack4h(v);
}

__global__ void convW(const float* __restrict__ Wg, const float* __restrict__ Wo) {
    __shared__ float tile[32][33];
    const int g = blockIdx.z;
    const float* W = g ? Wo : Wg;
    const int kb = blockIdx.x * 32, nb = blockIdx.y * 32;
    for (int i = threadIdx.y; i < 32; i += 8)
        tile[i][threadIdx.x] = W[(size_t)(kb + i) * DLAT + nb + threadIdx.x];
    __syncthreads();
    const int k = kb + threadIdx.x;
    for (int i = threadIdx.y; i < 32; i += 8) {
        __half h = __float2half_rn(tile[threadIdx.x][i]);
        const int n = nb + i;
        if (k < DLAT)
            g_B1[(size_t)g * DLAT * DLAT + (size_t)n * DLAT + k] = h;
        else
            g_B2[(size_t)g * DLAT * DFEAT + (size_t)n * DFEAT + (k - DLAT)] = h;
    }
}

// ---------------- GEMM: mode 1 = fp32 C raw ; mode 2 = fp32 C + bias + pf2u gather ----------------
extern __shared__ char dynsmem[];

__device__ __forceinline__ void load_chunk(uint32_t sbase, int stage, int kglob, int kdim,
                                           const __half* A, const __half* B,
                                           int m0, int n0, int tid) {
    const uint32_t st = sbase + stage * STG_BYTES;
    #pragma unroll
    for (int p = 0; p < 4; p++) {
        int lin = p * 256 + tid;
        int row = lin >> 3, kg = lin & 7;
        cp16(st + swz(row, kg), A + (size_t)(m0 + row) * kdim + kglob + kg * 8);
    }
    #pragma unroll
    for (int p = 0; p < 4; p++) {
        int lin = p * 256 + tid;
        int row = lin >> 3, kg = lin & 7;
        cp16(st + 16384 + swz(row, kg), B + (size_t)(n0 + row) * kdim + kglob + kg * 8);
    }
}

__global__ void __launch_bounds__(256, 2)
gemm_mma(const __half* __restrict__ Abase, const __half* __restrict__ Bbase,
         float* __restrict__ Cbase,
         const float* __restrict__ bg, const float* __restrict__ bo,
         int kdim, int nch,
         size_t strideAz, size_t strideBz, size_t strideCz, int mode) {
    const int z = blockIdx.z;
    const int n0 = blockIdx.x * BN;
    const int m0 = blockIdx.y * BM;
    const int tid = threadIdx.x;
    const int wid = tid >> 5;
    const int lane = tid & 31;
    const int wm = wid & 1;
    const int wn = wid >> 1;

    const __half* A = Abase + (size_t)z * strideAz;
    const __half* B = Bbase + (size_t)z * strideBz;
    float* C = Cbase + (size_t)z * strideCz;
    const float* bias = z ? bo : bg;

    const uint32_t sbase = smem_u32(dynsmem);

    float acc[4][4][4];
    #pragma unroll
    for (int i = 0; i < 4; i++)
        #pragma unroll
        for (int j = 0; j < 4; j++)
            #pragma unroll
            for (int r = 0; r < 4; r++) acc[i][j][r] = 0.0f;

    const int a_rb = wm * 64 + (lane & 15);
    const int a_gs = lane >> 4;
    const int b_rb = wn * 32 + (lane & 7) + ((lane & 16) >> 1);
    const int b_gs = (lane >> 3) & 1;

    load_chunk(sbase, 0, 0, kdim, A, B, m0, n0, tid); CP_COMMIT();
    load_chunk(sbase, 1, BK, kdim, A, B, m0, n0, tid); CP_COMMIT();

    for (int kc = 0; kc < nch; kc++) {
        CP_WAIT1();
        __syncthreads();
        if (kc + 2 < nch)
            load_chunk(sbase, (kc + 2) % NSTG, (kc + 2) * BK, kdim, A, B, m0, n0, tid);
        CP_COMMIT();

        const uint32_t sA = sbase + (kc % NSTG) * STG_BYTES;
        const uint32_t sB = sA + 16384;
        #pragma unroll
        for (int k4 = 0; k4 < 4; k4++) {
            uint32_t a[4][4];
            #pragma unroll
            for (int mi = 0; mi < 4; mi++)
                ldmx4(sA + swz(a_rb + mi * 16, k4 * 2 + a_gs),
                      a[mi][0], a[mi][1], a[mi][2], a[mi][3]);
            #pragma unroll
            for (int npp = 0; npp < 2; npp++) {
                uint32_t b0, b1, b2, b3;
                ldmx4(sB + swz(b_rb + npp * 16, k4 * 2 + b_gs), b0, b1, b2, b3);
                #pragma unroll
                for (int mi = 0; mi < 4; mi++) {
                    mma16816(acc[mi][npp*2][0], acc[mi][npp*2][1], acc[mi][npp*2][2], acc[mi][npp*2][3],
                             a[mi][0], a[mi][1], a[mi][2], a[mi][3], b0, b1);
                    mma16816(acc[mi][npp*2+1][0], acc[mi][npp*2+1][1], acc[mi][npp*2+1][2], acc[mi][npp*2+1][3],
                             a[mi][0], a[mi][1], a[mi][2], a[mi][3], b2, b3);
                }
            }
        }
    }

    // epilogue
    const int row_in = lane >> 2;
    const int col_in = (lane & 3) * 2;

    int gi0[4], gi1[4];
    const float* pfz = g_pf2u + (size_t)z * N_ * DLAT;
    if (mode == 2) {
        const int* m2 = g_match2 + (size_t)z * (P_ * T_);
        #pragma unroll
        for (int mi = 0; mi < 4; mi++) {
            const int r0 = m0 + wm * 64 + mi * 16 + row_in;
            gi0[mi] = __ldg(m2 + r0);
            gi1[mi] = __ldg(m2 + r0 + 8);
        }
    }

    #pragma unroll
    for (int np = 0; np < 4; np++) {
        const int col = n0 + wn * 32 + np * 8 + col_in;
        float bx = 0.0f, by = 0.0f;
        if (mode != 1) { bx = __ldg(bias + col); by = __ldg(bias + col + 1); }
        #pragma unroll
        for (int mi = 0; mi < 4; mi++) {
            const int r0 = m0 + wm * 64 + mi * 16 + row_in;
            float2 c0 = make_float2(acc[mi][np][0] + bx, acc[mi][np][1] + by);
            float2 c1 = make_float2(acc[mi][np][2] + bx, acc[mi][np][3] + by);
            if (mode == 2) {
                float2 p0 = *(const float2*)(pfz + (size_t)gi0[mi] * DLAT + col);
                float2 p1 = *(const float2*)(pfz + (size_t)gi1[mi] * DLAT + col);
                c0.x += p0.x; c0.y += p0.y;
                c1.x += p1.x; c1.y += p1.y;
            }
            *(float2*)(C + (size_t)r0 * DLAT + col) = c0;
            *(float2*)(C + (size_t)(r0 + 8) * DLAT + col) = c1;
        }
    }
}

// ---------------- launch ----------------
extern "C" void kernel_launch(void* const* d_in, const int* in_sizes, int n_in,
                              void* d_out, int out_size) {
    const float* object_surface = (const float*)d_in[0];
    const float* pre_pts        = (const float*)d_in[1];
    const float* pre_feats      = (const float*)d_in[2];
    const float* geo_raw        = (const float*)d_in[3];
    const float* obj_raw        = (const float*)d_in[4];
    const float* local_pc       = (const float*)d_in[5];
    const float* global_pc      = (const float*)d_in[6];
    const float* Wg             = (const float*)d_in[7];
    const float* bg             = (const float*)d_in[8];
    const float* Wo             = (const float*)d_in[9];
    const float* bo             = (const float*)d_in[10];
    float* out = (float*)d_out;

    static cudaStream_t s2 = nullptr, s3 = nullptr;
    static cudaEvent_t evFork = nullptr, evNN = nullptr, evMatch = nullptr, evA = nullptr;
    static bool inited = false;
    if (!inited) {
        cudaFuncSetAttribute(gemm_mma, cudaFuncAttributeMaxDynamicSharedMemorySize, GEMM_SMEM);
        cudaStreamCreateWithFlags(&s2, cudaStreamNonBlocking);
        cudaStreamCreateWithFlags(&s3, cudaStreamNonBlocking);
        cudaEventCreateWithFlags(&evFork, cudaEventDisableTiming);
        cudaEventCreateWithFlags(&evNN, cudaEventDisableTiming);
        cudaEventCreateWithFlags(&evMatch, cudaEventDisableTiming);
        cudaEventCreateWithFlags(&evA, cudaEventDisableTiming);
        inited = true;
    }

    __half* gA  = nullptr; cudaGetSymbolAddress((void**)&gA,  g_A);
    __half* gPF = nullptr; cudaGetSymbolAddress((void**)&gPF, g_PF);
    __half* gB1 = nullptr; cudaGetSymbolAddress((void**)&gB1, g_B1);
    __half* gB2 = nullptr; cudaGetSymbolAddress((void**)&gB2, g_B2);
    float* gPU  = nullptr; cudaGetSymbolAddress((void**)&gPU, g_pf2u);

    // fork
    cudaEventRecord(evFork, 0);
    cudaStreamWaitEvent(s2, evFork, 0);
    cudaStreamWaitEvent(s3, evFork, 0);

    // s2: nn1 -> match (serial, as in round 12)
    nn1_partial<<<dim3(N_ / 1024, MSPLIT), 256, 0, s2>>>(object_surface, pre_pts);
    nn1_reduce<<<N_ / 256, 256, 0, s2>>>();
    cudaEventRecord(evNN, s2);
    match_partial<<<dim3(1, P_, 2 * NSCH), 256, 0, s2>>>(object_surface, local_pc, global_pc);
    match_reduce<<<2 * P_ * T_ / 256, 256, 0, s2>>>();
    cudaEventRecord(evMatch, s2);

    // s3: convA (DRAM-bound, off the pf2u critical chain)
    convA<<<dim3(P_ * T_, 2), 256, 0, s3>>>(geo_raw, obj_raw);
    cudaEventRecord(evA, s3);

    // s0: convW -> (wait nn1) gatherPF -> pf2u GEMM -> (wait match, convA) main GEMM
    convW<<<dim3(DIN / 32, DLAT / 32, 2), dim3(32, 8)>>>(Wg, Wo);
    cudaStreamWaitEvent(0, evNN, 0);
    gatherPF<<<N_, DFEAT / 4>>>(pre_feats);
    gemm_mma<<<dim3(DLAT / BN, N_ / BM, 2), 256, GEMM_SMEM>>>(
        gPF, gB2, gPU, nullptr, nullptr,
        DFEAT, DFEAT / BK, 0, (size_t)DLAT * DFEAT, (size_t)N_ * DLAT, 1);

    cudaStreamWaitEvent(0, evMatch, 0);
    cudaStreamWaitEvent(0, evA, 0);
    gemm_mma<<<dim3(DLAT / BN, (P_ * T_) / BM, 2), 256, GEMM_SMEM>>>(
        gA, gB1, out, bg, bo,
        DLAT, DLAT / BK, (size_t)(P_ * T_) * DLAT, (size_t)DLAT * DLAT,
        (size_t)(P_ * T_) * DLAT, 2);
}

// round 15
// speedup vs baseline: 1.0600x; 1.0237x over previous
#include <cuda_runtime.h>
#include <cuda_fp16.h>
#include <cstdint>

#define P_    8
#define T_    2048
#define N_    8192
#define M_    20000
#define DLAT  1024
#define DFEAT 512
#define DIN   1536
#define MSPLIT 20
#define MCHUNK 1000
#define NSCH  8
#define SCHSZ 1024

// ---- GEMM config (round-5/8/12 proven shape) ----
#define BM 128
#define BN 128
#define BK 64
#define NSTG 3
#define STG_BYTES 32768                // A 16K + B 16K
#define GEMM_SMEM (NSTG * STG_BYTES)   // 96KB

// ---------------- scratch ----------------
__device__ float g_part_d[N_ * MSPLIT];
__device__ int   g_part_i[N_ * MSPLIT];
__device__ float g_mp_d[2 * P_ * NSCH * T_];
__device__ int   g_mp_i[2 * P_ * NSCH * T_];
__device__ int   g_match2[2 * P_ * T_];          // [which][p][t] -> obj-point idx
__device__ __half g_A[2L * P_ * T_ * DLAT];      // [z][m][k<1024] fp16
__device__ __half g_PF[(size_t)N_ * DFEAT];      // fp16 feats per obj point
__device__ __half g_B1[2L * DLAT * DLAT];        // W[:1024]^T fp16 [z][n][k]
__device__ __half g_B2[2L * DLAT * DFEAT];       // W[1024:]^T fp16 [z][n][k]
__device__ float g_pf2u[2L * N_ * DLAT];         // fp32 pf @ W2 per obj point

// ---------------- helpers ----------------
__device__ __forceinline__ uint32_t smem_u32(const void* p) {
    uint32_t a;
    asm("{ .reg .u64 t; cvta.to.shared.u64 t, %1; cvt.u32.u64 %0, t; }" : "=r"(a) : "l"(p));
    return a;
}
__device__ __forceinline__ void cp16(uint32_t dst, const void* src) {
    asm volatile("cp.async.cg.shared.global [%0], [%1], 16;" :: "r"(dst), "l"(src) : "memory");
}
#define CP_COMMIT() asm volatile("cp.async.commit_group;" ::: "memory")
#define CP_WAIT1()  asm volatile("cp.async.wait_group 1;" ::: "memory")

__device__ __forceinline__ void ldmx4(uint32_t addr, uint32_t& r0, uint32_t& r1,
                                      uint32_t& r2, uint32_t& r3) {
    asm volatile("ldmatrix.sync.aligned.m8n8.x4.shared.b16 {%0,%1,%2,%3}, [%4];"
                 : "=r"(r0), "=r"(r1), "=r"(r2), "=r"(r3) : "r"(addr));
}
__device__ __forceinline__ void mma16816(float& c0, float& c1, float& c2, float& c3,
                                         uint32_t a0, uint32_t a1, uint32_t a2, uint32_t a3,
                                         uint32_t b0, uint32_t b1) {
    asm volatile("mma.sync.aligned.m16n8k16.row.col.f32.f16.f16.f32 "
                 "{%0,%1,%2,%3}, {%4,%5,%6,%7}, {%8,%9}, {%0,%1,%2,%3};"
                 : "+f"(c0), "+f"(c1), "+f"(c2), "+f"(c3)
                 : "r"(a0), "r"(a1), "r"(a2), "r"(a3), "r"(b0), "r"(b1));
}
__device__ __forceinline__ uint32_t swz(int row, int kg) {
    return (uint32_t)(row * 128 + ((kg ^ (row & 7)) << 4));
}
__device__ __forceinline__ uint2 pack4h(float4 v) {
    __half hx = __float2half_rn(v.x), hy = __float2half_rn(v.y);
    __half hz = __float2half_rn(v.z), hw = __float2half_rn(v.w);
    uint2 r;
    r.x = ((uint32_t)*(uint16_t*)&hy << 16) | (uint32_t)*(uint16_t*)&hx;
    r.y = ((uint32_t)*(uint16_t*)&hw << 16) | (uint32_t)*(uint16_t*)&hz;
    return r;
}

// ---------------- kernel 1: obj_pts[0] vs precomputed_points ----------------
// grid (N/1024, MSPLIT), block 256, 4 q/thread, 1000-candidate chunks
__global__ void nn1_partial(const float* __restrict__ os, const float* __restrict__ pts) {
    __shared__ float4 sP[MCHUNK];
    const int ms = blockIdx.y;
    const int m0 = ms * MCHUNK;
    for (int i = threadIdx.x; i < MCHUNK; i += 256) {
        float x = pts[(size_t)(m0 + i) * 3 + 0];
        float y = pts[(size_t)(m0 + i) * 3 + 1];
        float z = pts[(size_t)(m0 + i) * 3 + 2];
        sP[i] = make_float4(x, y, z, x * x + y * y + z * z);
    }
    __syncthreads();
    float qx[4], qy[4], qz[4], best[4];
    int bi[4];
    #pragma unroll
    for (int u = 0; u < 4; u++) {
        const int q = blockIdx.x * 1024 + u * 256 + threadIdx.x;
        qx[u] = -2.0f * os[(size_t)q * 6 + 0];
        qy[u] = -2.0f * os[(size_t)q * 6 + 1];
        qz[u] = -2.0f * os[(size_t)q * 6 + 2];
        best[u] = 3.4e38f;
        bi[u] = 0;
    }
    #pragma unroll 4
    for (int i = 0; i < MCHUNK; i++) {
        float4 c = sP[i];
        #pragma unroll
        for (int u = 0; u < 4; u++) {
            float d = fmaf(qx[u], c.x, fmaf(qy[u], c.y, fmaf(qz[u], c.z, c.w)));
            if (d < best[u]) { best[u] = d; bi[u] = i; }
        }
    }
    #pragma unroll
    for (int u = 0; u < 4; u++) {
        const int q = blockIdx.x * 1024 + u * 256 + threadIdx.x;
        g_part_d[q * MSPLIT + ms] = best[u];
        g_part_i[q * MSPLIT + ms] = m0 + bi[u];
    }
}

// fused nn1_reduce + gatherPF: block q reduces its 20 partials (broadcast loads),
// then all 128 threads gather the 512-float feature row -> fp16 PF table.
__global__ void reduce_gatherPF(const float* __restrict__ pf) {
    const int q = blockIdx.x;
    float best = g_part_d[q * MSPLIT];
    int bi = g_part_i[q * MSPLIT];
    #pragma unroll
    for (int s = 1; s < MSPLIT; s++) {
        float d = g_part_d[q * MSPLIT + s];
        if (d < best) { best = d; bi = g_part_i[q * MSPLIT + s]; }
    }
    float4 v = *(const float4*)(pf + (size_t)bi * DFEAT + threadIdx.x * 4);
    *(uint2*)(g_PF + (size_t)q * DFEAT + threadIdx.x * 4) = pack4h(v);
}

// ---------------- kernel 2: match partial (4 q/thread) + reduce ----------------
__global__ void match_partial(const float* __restrict__ os,
                              const float* __restrict__ local_pc,
                              const float* __restrict__ global_pc) {
    __shared__ float4 sP[SCHSZ];
    const int p = blockIdx.y;
    const int which = blockIdx.z >> 3;
    const int ch = blockIdx.z & 7;
    const int nt = ch * SCHSZ;
    const float* qsrc = (which == 0) ? local_pc : global_pc;
    const int tb = blockIdx.x * 1024 + threadIdx.x;

    for (int i = threadIdx.x; i < SCHSZ; i += 256) {
        size_t bsrc = ((size_t)p * N_ + nt + i) * 6;
        float x = os[bsrc + 0], y = os[bsrc + 1], z = os[bsrc + 2];
        sP[i] = make_float4(x, y, z, x * x + y * y + z * z);
    }

    float qx[4], qy[4], qz[4], best[4];
    int bi[4];
    #pragma unroll
    for (int u = 0; u < 4; u++) {
        const size_t qb = ((size_t)p * T_ + tb + u * 256) * 3;
        qx[u] = -2.0f * qsrc[qb + 0];
        qy[u] = -2.0f * qsrc[qb + 1];
        qz[u] = -2.0f * qsrc[qb + 2];
        best[u] = 3.4e38f;
        bi[u] = 0;
    }
    __syncthreads();
    #pragma unroll 4
    for (int i = 0; i < SCHSZ; i++) {
        float4 c = sP[i];
        #pragma unroll
        for (int u = 0; u < 4; u++) {
            float d = fmaf(qx[u], c.x, fmaf(qy[u], c.y, fmaf(qz[u], c.z, c.w)));
            if (d < best[u]) { best[u] = d; bi[u] = nt + i; }
        }
    }
    #pragma unroll
    for (int u = 0; u < 4; u++) {
        size_t o = (((size_t)which * P_ + p) * NSCH + ch) * T_ + tb + u * 256;
        g_mp_d[o] = best[u];
        g_mp_i[o] = bi[u];
    }
}

__global__ void match_reduce() {
    const int g = blockIdx.x * 256 + threadIdx.x;
    const int wp = g / T_;
    const int t = g % T_;
    size_t base = ((size_t)wp * NSCH) * T_ + t;
    float best = g_mp_d[base];
    int bi = g_mp_i[base];
    #pragma unroll
    for (int c = 1; c < NSCH; c++) {
        float d = g_mp_d[base + (size_t)c * T_];
        if (d < best) { best = d; bi = g_mp_i[base + (size_t)c * T_]; }
    }
    g_match2[g] = bi;
}

// ---------------- fused prep: convA (blocks 0..32767) + convW (blocks 32768..35839) ----------------
__global__ void prep(const float* __restrict__ geo_raw, const float* __restrict__ obj_raw,
                     const float* __restrict__ Wg, const float* __restrict__ Wo) {
    __shared__ float tile[32][33];
    const int bid = blockIdx.x;
    if (bid < 2 * P_ * T_) {
        // convA: raw fp32 -> fp16 A[k<1024]
        const int z = bid >> 14;            // /16384
        const int m = bid & 16383;
        const float* src = (z ? obj_raw : geo_raw) + (size_t)m * DLAT + threadIdx.x * 4;
        float4 v = *(const float4*)src;
        size_t base = ((size_t)z * (P_ * T_) + m) * DLAT + threadIdx.x * 4;
        *(uint2*)(g_A + base) = pack4h(v);
    } else {
        // convW: W transpose -> fp16 [n][k], split at k=1024
        const int idx = bid - 2 * P_ * T_;        // 0..3071
        const int g = idx / 1536;
        const int rem = idx % 1536;
        const int kb = (rem % 48) * 32;
        const int nb = (rem / 48) * 32;
        const float* W = g ? Wo : Wg;
        const int tx = threadIdx.x & 31;
        const int ty = threadIdx.x >> 5;          // 0..7
        for (int i = ty; i < 32; i += 8)
            tile[i][tx] = W[(size_t)(kb + i) * DLAT + nb + tx];
        __syncthreads();
        const int k = kb + tx;
        for (int i = ty; i < 32; i += 8) {
            __half h = __float2half_rn(tile[tx][i]);
            const int n = nb + i;
            if (k < DLAT)
                g_B1[(size_t)g * DLAT * DLAT + (size_t)n * DLAT + k] = h;
            else
                g_B2[(size_t)g * DLAT * DFEAT + (size_t)n * DFEAT + (k - DLAT)] = h;
        }
    }
}

// ---------------- GEMM: mode 1 = fp32 C raw ; mode 2 = fp32 C + bias + pf2u gather ----------------
extern __shared__ char dynsmem[];

__device__ __forceinline__ void load_chunk(uint32_t sbase, int stage, int kglob, int kdim,
                                           const __half* A, const __half* B,
                                           int m0, int n0, int tid) {
    const uint32_t st = sbase + stage * STG_BYTES;
    #pragma unroll
    for (int p = 0; p < 4; p++) {
        int lin = p * 256 + tid;
        int row = lin >> 3, kg = lin & 7;
        cp16(st + swz(row, kg), A + (size_t)(m0 + row) * kdim + kglob + kg * 8);
    }
    #pragma unroll
    for (int p = 0; p < 4; p++) {
        int lin = p * 256 + tid;
        int row = lin >> 3, kg = lin & 7;
        cp16(st + 16384 + swz(row, kg), B + (size_t)(n0 + row) * kdim + kglob + kg * 8);
    }
}

__global__ void __launch_bounds__(256, 2)
gemm_mma(const __half* __restrict__ Abase, const __half* __restrict__ Bbase,
         float* __restrict__ Cbase,
         const float* __restrict__ bg, const float* __restrict__ bo,
         int kdim, int nch,
         size_t strideAz, size_t strideBz, size_t strideCz, int mode) {
    const int z = blockIdx.z;
    const int n0 = blockIdx.x * BN;
    const int m0 = blockIdx.y * BM;
    const int tid = threadIdx.x;
    const int wid = tid >> 5;
    const int lane = tid & 31;
    const int wm = wid & 1;
    const int wn = wid >> 1;

    const __half* A = Abase + (size_t)z * strideAz;
    const __half* B = Bbase + (size_t)z * strideBz;
    float* C = Cbase + (size_t)z * strideCz;
    const float* bias = z ? bo : bg;

    const uint32_t sbase = smem_u32(dynsmem);

    float acc[4][4][4];
    #pragma unroll
    for (int i = 0; i < 4; i++)
        #pragma unroll
        for (int j = 0; j < 4; j++)
            #pragma unroll
            for (int r = 0; r < 4; r++) acc[i][j][r] = 0.0f;

    const int a_rb = wm * 64 + (lane & 15);
    const int a_gs = lane >> 4;
    const int b_rb = wn * 32 + (lane & 7) + ((lane & 16) >> 1);
    const int b_gs = (lane >> 3) & 1;

    load_chunk(sbase, 0, 0, kdim, A, B, m0, n0, tid); CP_COMMIT();
    load_chunk(sbase, 1, BK, kdim, A, B, m0, n0, tid); CP_COMMIT();

    for (int kc = 0; kc < nch; kc++) {
        CP_WAIT1();
        __syncthreads();
        if (kc + 2 < nch)
            load_chunk(sbase, (kc + 2) % NSTG, (kc + 2) * BK, kdim, A, B, m0, n0, tid);
        CP_COMMIT();

        const uint32_t sA = sbase + (kc % NSTG) * STG_BYTES;
        const uint32_t sB = sA + 16384;
        #pragma unroll
        for (int k4 = 0; k4 < 4; k4++) {
            uint32_t a[4][4];
            #pragma unroll
            for (int mi = 0; mi < 4; mi++)
                ldmx4(sA + swz(a_rb + mi * 16, k4 * 2 + a_gs),
                      a[mi][0], a[mi][1], a[mi][2], a[mi][3]);
            #pragma unroll
            for (int npp = 0; npp < 2; npp++) {
                uint32_t b0, b1, b2, b3;
                ldmx4(sB + swz(b_rb + npp * 16, k4 * 2 + b_gs), b0, b1, b2, b3);
                #pragma unroll
                for (int mi = 0; mi < 4; mi++) {
                    mma16816(acc[mi][npp*2][0], acc[mi][npp*2][1], acc[mi][npp*2][2], acc[mi][npp*2][3],
                             a[mi][0], a[mi][1], a[mi][2], a[mi][3], b0, b1);
                    mma16816(acc[mi][npp*2+1][0], acc[mi][npp*2+1][1], acc[mi][npp*2+1][2], acc[mi][npp*2+1][3],
                             a[mi][0], a[mi][1], a[mi][2], a[mi][3], b2, b3);
                }
            }
        }
    }

    // epilogue
    const int row_in = lane >> 2;
    const int col_in = (lane & 3) * 2;

    int gi0[4], gi1[4];
    const float* pfz = g_pf2u + (size_t)z * N_ * DLAT;
    if (mode == 2) {
        const int* m2 = g_match2 + (size_t)z * (P_ * T_);
        #pragma unroll
        for (int mi = 0; mi < 4; mi++) {
            const int r0 = m0 + wm * 64 + mi * 16 + row_in;
            gi0[mi] = __ldg(m2 + r0);
            gi1[mi] = __ldg(m2 + r0 + 8);
        }
    }

    #pragma unroll
    for (int np = 0; np < 4; np++) {
        const int col = n0 + wn * 32 + np * 8 + col_in;
        float bx = 0.0f, by = 0.0f;
        if (mode != 1) { bx = __ldg(bias + col); by = __ldg(bias + col + 1); }
        #pragma unroll
        for (int mi = 0; mi < 4; mi++) {
            const int r0 = m0 + wm * 64 + mi * 16 + row_in;
            float2 c0 = make_float2(acc[mi][np][0] + bx, acc[mi][np][1] + by);
            float2 c1 = make_float2(acc[mi][np][2] + bx, acc[mi][np][3] + by);
            if (mode == 2) {
                float2 p0 = *(const float2*)(pfz + (size_t)gi0[mi] * DLAT + col);
                float2 p1 = *(const float2*)(pfz + (size_t)gi1[mi] * DLAT + col);
                c0.x += p0.x; c0.y += p0.y;
                c1.x += p1.x; c1.y += p1.y;
            }
            *(float2*)(C + (size_t)r0 * DLAT + col) = c0;
            *(float2*)(C + (size_t)(r0 + 8) * DLAT + col) = c1;
        }
    }
}

// ---------------- launch (round-12 schedule, fused kernels) ----------------
extern "C" void kernel_launch(void* const* d_in, const int* in_sizes, int n_in,
                              void* d_out, int out_size) {
    const float* object_surface = (const float*)d_in[0];
    const float* pre_pts        = (const float*)d_in[1];
    const float* pre_feats      = (const float*)d_in[2];
    const float* geo_raw        = (const float*)d_in[3];
    const float* obj_raw        = (const float*)d_in[4];
    const float* local_pc       = (const float*)d_in[5];
    const float* global_pc      = (const float*)d_in[6];
    const float* Wg             = (const float*)d_in[7];
    const float* bg             = (const float*)d_in[8];
    const float* Wo             = (const float*)d_in[9];
    const float* bo             = (const float*)d_in[10];
    float* out = (float*)d_out;

    static cudaStream_t s2 = nullptr;
    static cudaEvent_t evFork = nullptr, evNN = nullptr, evMatch = nullptr;
    static bool inited = false;
    if (!inited) {
        cudaFuncSetAttribute(gemm_mma, cudaFuncAttributeMaxDynamicSharedMemorySize, GEMM_SMEM);
        cudaStreamCreateWithFlags(&s2, cudaStreamNonBlocking);
        cudaEventCreateWithFlags(&evFork, cudaEventDisableTiming);
        cudaEventCreateWithFlags(&evNN, cudaEventDisableTiming);
        cudaEventCreateWithFlags(&evMatch, cudaEventDisableTiming);
        inited = true;
    }

    __half* gA  = nullptr; cudaGetSymbolAddress((void**)&gA,  g_A);
    __half* gPF = nullptr; cudaGetSymbolAddress((void**)&gPF, g_PF);
    __half* gB1 = nullptr; cudaGetSymbolAddress((void**)&gB1, g_B1);
    __half* gB2 = nullptr; cudaGetSymbolAddress((void**)&gB2, g_B2);
    float* gPU  = nullptr; cudaGetSymbolAddress((void**)&gPU, g_pf2u);

    // fork: NN chain on s2
    cudaEventRecord(evFork, 0);
    cudaStreamWaitEvent(s2, evFork, 0);

    nn1_partial<<<dim3(N_ / 1024, MSPLIT), 256, 0, s2>>>(object_surface, pre_pts);
    cudaEventRecord(evNN, s2);
    match_partial<<<dim3(T_ / 1024, P_, 2 * NSCH), 256, 0, s2>>>(object_surface, local_pc, global_pc);
    match_reduce<<<2 * P_ * T_ / 256, 256, 0, s2>>>();
    cudaEventRecord(evMatch, s2);

    // main stream: fused prep (convA + convW), then pf2u chain (after nn1), then big GEMM
    prep<<<2 * P_ * T_ + 2 * 1536, 256>>>(geo_raw, obj_raw, Wg, Wo);

    cudaStreamWaitEvent(0, evNN, 0);
    reduce_gatherPF<<<N_, DFEAT / 4>>>(pre_feats);
    // pf2u[z] = g_PF @ g_B2[z]  (M=8192, N=1024, K=512), raw fp32 write
    gemm_mma<<<dim3(DLAT / BN, N_ / BM, 2), 256, GEMM_SMEM>>>(
        gPF, gB2, gPU, nullptr, nullptr,
        DFEAT, DFEAT / BK, 0, (size_t)DLAT * DFEAT, (size_t)N_ * DLAT, 1);

    cudaStreamWaitEvent(0, evMatch, 0);
    // C[z] = A[z] @ B1[z] + bias[z] + pf2u[z][match2]  (M=16384, N=1024, K=1024)
    gemm_mma<<<dim3(DLAT / BN, (P_ * T_) / BM, 2), 256, GEMM_SMEM>>>(
        gA, gB1, out, bg, bo,
        DLAT, DLAT / BK, (size_t)(P_ * T_) * DLAT, (size_t)DLAT * DLAT,
        (size_t)(P_ * T_) * DLAT, 2);
}

// round 16
// speedup vs baseline: 1.1236x; 1.0600x over previous
#include <cuda_runtime.h>
#include <cuda_fp16.h>
#include <cstdint>

#define P_    8
#define T_    2048
#define N_    8192
#define M_    20000
#define DLAT  1024
#define DFEAT 512
#define DIN   1536
#define MSPLIT 20
#define MCHUNK 1000
#define NSCH  8
#define SCHSZ 1024

// ---- GEMM config (round-5/8/12 proven shape) ----
#define BM 128
#define BN 128
#define BK 64
#define NSTG 3
#define STG_BYTES 32768                // A 16K + B 16K
#define GEMM_SMEM (NSTG * STG_BYTES)   // 96KB

// ---------------- scratch ----------------
__device__ float g_part_d[N_ * MSPLIT];
__device__ int   g_part_i[N_ * MSPLIT];
__device__ float g_mp_d[2 * P_ * NSCH * T_];
__device__ int   g_mp_i[2 * P_ * NSCH * T_];
__device__ int   g_match2[2 * P_ * T_];          // [which][p][t] -> obj-point idx
__device__ __half g_A[2L * P_ * T_ * DLAT];      // [z][m][k<1024] fp16
__device__ __half g_PF[(size_t)N_ * DFEAT];      // fp16 feats per obj point
__device__ __half g_B1[2L * DLAT * DLAT];        // W[:1024]^T fp16 [z][n][k]
__device__ __half g_B2[2L * DLAT * DFEAT];       // W[1024:]^T fp16 [z][n][k]
__device__ float g_pf2u[2L * N_ * DLAT];         // fp32 pf @ W2 per obj point

// ---------------- helpers ----------------
__device__ __forceinline__ uint32_t smem_u32(const void* p) {
    uint32_t a;
    asm("{ .reg .u64 t; cvta.to.shared.u64 t, %1; cvt.u32.u64 %0, t; }" : "=r"(a) : "l"(p));
    return a;
}
__device__ __forceinline__ void cp16(uint32_t dst, const void* src) {
    asm volatile("cp.async.cg.shared.global [%0], [%1], 16;" :: "r"(dst), "l"(src) : "memory");
}
#define CP_COMMIT() asm volatile("cp.async.commit_group;" ::: "memory")
#define CP_WAIT1()  asm volatile("cp.async.wait_group 1;" ::: "memory")

__device__ __forceinline__ void ldmx4(uint32_t addr, uint32_t& r0, uint32_t& r1,
                                      uint32_t& r2, uint32_t& r3) {
    asm volatile("ldmatrix.sync.aligned.m8n8.x4.shared.b16 {%0,%1,%2,%3}, [%4];"
                 : "=r"(r0), "=r"(r1), "=r"(r2), "=r"(r3) : "r"(addr));
}
__device__ __forceinline__ void mma16816(float& c0, float& c1, float& c2, float& c3,
                                         uint32_t a0, uint32_t a1, uint32_t a2, uint32_t a3,
                                         uint32_t b0, uint32_t b1) {
    asm volatile("mma.sync.aligned.m16n8k16.row.col.f32.f16.f16.f32 "
                 "{%0,%1,%2,%3}, {%4,%5,%6,%7}, {%8,%9}, {%0,%1,%2,%3};"
                 : "+f"(c0), "+f"(c1), "+f"(c2), "+f"(c3)
                 : "r"(a0), "r"(a1), "r"(a2), "r"(a3), "r"(b0), "r"(b1));
}
__device__ __forceinline__ uint32_t swz(int row, int kg) {
    return (uint32_t)(row * 128 + ((kg ^ (row & 7)) << 4));
}
__device__ __forceinline__ uint2 pack4h(float4 v) {
    __half hx = __float2half_rn(v.x), hy = __float2half_rn(v.y);
    __half hz = __float2half_rn(v.z), hw = __float2half_rn(v.w);
    uint2 r;
    r.x = ((uint32_t)*(uint16_t*)&hy << 16) | (uint32_t)*(uint16_t*)&hx;
    r.y = ((uint32_t)*(uint16_t*)&hw << 16) | (uint32_t)*(uint16_t*)&hz;
    return r;
}

// ---------------- kernel 1: obj_pts[0] vs precomputed_points ----------------
__global__ void nn1_partial(const float* __restrict__ os, const float* __restrict__ pts) {
    __shared__ float4 sP[MCHUNK];
    const int ms = blockIdx.y;
    const int m0 = ms * MCHUNK;
    for (int i = threadIdx.x; i < MCHUNK; i += 256) {
        float x = pts[(size_t)(m0 + i) * 3 + 0];
        float y = pts[(size_t)(m0 + i) * 3 + 1];
        float z = pts[(size_t)(m0 + i) * 3 + 2];
        sP[i] = make_float4(x, y, z, x * x + y * y + z * z);
    }
    __syncthreads();
    float qx[4], qy[4], qz[4], best[4];
    int bi[4];
    #pragma unroll
    for (int u = 0; u < 4; u++) {
        const int q = blockIdx.x * 1024 + u * 256 + threadIdx.x;
        qx[u] = -2.0f * os[(size_t)q * 6 + 0];
        qy[u] = -2.0f * os[(size_t)q * 6 + 1];
        qz[u] = -2.0f * os[(size_t)q * 6 + 2];
        best[u] = 3.4e38f;
        bi[u] = 0;
    }
    #pragma unroll 4
    for (int i = 0; i < MCHUNK; i++) {
        float4 c = sP[i];
        #pragma unroll
        for (int u = 0; u < 4; u++) {
            float d = fmaf(qx[u], c.x, fmaf(qy[u], c.y, fmaf(qz[u], c.z, c.w)));
            if (d < best[u]) { best[u] = d; bi[u] = i; }
        }
    }
    #pragma unroll
    for (int u = 0; u < 4; u++) {
        const int q = blockIdx.x * 1024 + u * 256 + threadIdx.x;
        g_part_d[q * MSPLIT + ms] = best[u];
        g_part_i[q * MSPLIT + ms] = m0 + bi[u];
    }
}

// fused nn1_reduce + gatherPF
__global__ void reduce_gatherPF(const float* __restrict__ pf) {
    const int q = blockIdx.x;
    float best = g_part_d[q * MSPLIT];
    int bi = g_part_i[q * MSPLIT];
    #pragma unroll
    for (int s = 1; s < MSPLIT; s++) {
        float d = g_part_d[q * MSPLIT + s];
        if (d < best) { best = d; bi = g_part_i[q * MSPLIT + s]; }
    }
    float4 v = *(const float4*)(pf + (size_t)bi * DFEAT + threadIdx.x * 4);
    *(uint2*)(g_PF + (size_t)q * DFEAT + threadIdx.x * 4) = pack4h(v);
}

// ---------------- kernel 2: match partial (4 q/thread) + reduce ----------------
__global__ void match_partial(const float* __restrict__ os,
                              const float* __restrict__ local_pc,
                              const float* __restrict__ global_pc) {
    __shared__ float4 sP[SCHSZ];
    const int p = blockIdx.y;
    const int which = blockIdx.z >> 3;
    const int ch = blockIdx.z & 7;
    const int nt = ch * SCHSZ;
    const float* qsrc = (which == 0) ? local_pc : global_pc;
    const int tb = blockIdx.x * 1024 + threadIdx.x;

    for (int i = threadIdx.x; i < SCHSZ; i += 256) {
        size_t bsrc = ((size_t)p * N_ + nt + i) * 6;
        float x = os[bsrc + 0], y = os[bsrc + 1], z = os[bsrc + 2];
        sP[i] = make_float4(x, y, z, x * x + y * y + z * z);
    }

    float qx[4], qy[4], qz[4], best[4];
    int bi[4];
    #pragma unroll
    for (int u = 0; u < 4; u++) {
        const size_t qb = ((size_t)p * T_ + tb + u * 256) * 3;
        qx[u] = -2.0f * qsrc[qb + 0];
        qy[u] = -2.0f * qsrc[qb + 1];
        qz[u] = -2.0f * qsrc[qb + 2];
        best[u] = 3.4e38f;
        bi[u] = 0;
    }
    __syncthreads();
    #pragma unroll 4
    for (int i = 0; i < SCHSZ; i++) {
        float4 c = sP[i];
        #pragma unroll
        for (int u = 0; u < 4; u++) {
            float d = fmaf(qx[u], c.x, fmaf(qy[u], c.y, fmaf(qz[u], c.z, c.w)));
            if (d < best[u]) { best[u] = d; bi[u] = nt + i; }
        }
    }
    #pragma unroll
    for (int u = 0; u < 4; u++) {
        size_t o = (((size_t)which * P_ + p) * NSCH + ch) * T_ + tb + u * 256;
        g_mp_d[o] = best[u];
        g_mp_i[o] = bi[u];
    }
}

__global__ void match_reduce() {
    const int g = blockIdx.x * 256 + threadIdx.x;
    const int wp = g / T_;
    const int t = g % T_;
    size_t base = ((size_t)wp * NSCH) * T_ + t;
    float best = g_mp_d[base];
    int bi = g_mp_i[base];
    #pragma unroll
    for (int c = 1; c < NSCH; c++) {
        float d = g_mp_d[base + (size_t)c * T_];
        if (d < best) { best = d; bi = g_mp_i[base + (size_t)c * T_]; }
    }
    g_match2[g] = bi;
}

// ---------------- fused prep: convA (blocks 0..32767) + convW (rest) ----------------
__global__ void prep(const float* __restrict__ geo_raw, const float* __restrict__ obj_raw,
                     const float* __restrict__ Wg, const float* __restrict__ Wo) {
    __shared__ float tile[32][33];
    const int bid = blockIdx.x;
    if (bid < 2 * P_ * T_) {
        const int z = bid >> 14;
        const int m = bid & 16383;
        const float* src = (z ? obj_raw : geo_raw) + (size_t)m * DLAT + threadIdx.x * 4;
        float4 v = *(const float4*)src;
        size_t base = ((size_t)z * (P_ * T_) + m) * DLAT + threadIdx.x * 4;
        *(uint2*)(g_A + base) = pack4h(v);
    } else {
        const int idx = bid - 2 * P_ * T_;
        const int g = idx / 1536;
        const int rem = idx % 1536;
        const int kb = (rem % 48) * 32;
        const int nb = (rem / 48) * 32;
        const float* W = g ? Wo : Wg;
        const int tx = threadIdx.x & 31;
        const int ty = threadIdx.x >> 5;
        for (int i = ty; i < 32; i += 8)
            tile[i][tx] = W[(size_t)(kb + i) * DLAT + nb + tx];
        __syncthreads();
        const int k = kb + tx;
        for (int i = ty; i < 32; i += 8) {
            __half h = __float2half_rn(tile[tx][i]);
            const int n = nb + i;
            if (k < DLAT)
                g_B1[(size_t)g * DLAT * DLAT + (size_t)n * DLAT + k] = h;
            else
                g_B2[(size_t)g * DLAT * DFEAT + (size_t)n * DFEAT + (k - DLAT)] = h;
        }
    }
}

// ---------------- GEMM with strength-reduced loader ----------------
// mode 1 = fp32 C raw ; mode 2 = fp32 C + bias + pf2u gather
extern __shared__ char dynsmem[];

__global__ void __launch_bounds__(256, 2)
gemm_mma(const __half* __restrict__ Abase, const __half* __restrict__ Bbase,
         float* __restrict__ Cbase,
         const float* __restrict__ bg, const float* __restrict__ bo,
         int kdim, int nch,
         size_t strideAz, size_t strideBz, size_t strideCz, int mode) {
    const int z = blockIdx.z;
    const int n0 = blockIdx.x * BN;
    const int m0 = blockIdx.y * BM;
    const int tid = threadIdx.x;
    const int wid = tid >> 5;
    const int lane = tid & 31;
    const int wm = wid & 1;
    const int wn = wid >> 1;

    float* C = Cbase + (size_t)z * strideCz;
    const float* bias = z ? bo : bg;

    const uint32_t sbase = smem_u32(dynsmem);

    // --- precomputed loader state (loop-invariant per thread) ---
    const int lrow = tid >> 3;          // 0..31
    const int lkg = tid & 7;            // granule
    const __half* pA[4];
    const __half* pB[4];
    uint32_t dA[4], dB[4];
    {
        const __half* A = Abase + (size_t)z * strideAz;
        const __half* B = Bbase + (size_t)z * strideBz;
        #pragma unroll
        for (int p = 0; p < 4; p++) {
            const int rw = lrow + p * 32;
            pA[p] = A + (size_t)(m0 + rw) * kdim + lkg * 8;
            pB[p] = B + (size_t)(n0 + rw) * kdim + lkg * 8;
            dA[p] = swz(rw, lkg);
            dB[p] = 16384u + swz(rw, lkg);
        }
    }

    float acc[4][4][4];
    #pragma unroll
    for (int i = 0; i < 4; i++)
        #pragma unroll
        for (int j = 0; j < 4; j++)
            #pragma unroll
            for (int r = 0; r < 4; r++) acc[i][j][r] = 0.0f;

    const int a_rb = wm * 64 + (lane & 15);
    const int a_gs = lane >> 4;
    const int b_rb = wn * 32 + (lane & 7) + ((lane & 16) >> 1);
    const int b_gs = (lane >> 3) & 1;

    // prologue: stages 0,1
    uint32_t st_load = sbase;
    #pragma unroll
    for (int s = 0; s < 2; s++) {
        #pragma unroll
        for (int p = 0; p < 4; p++) { cp16(st_load + dA[p], pA[p]); pA[p] += BK; }
        #pragma unroll
        for (int p = 0; p < 4; p++) { cp16(st_load + dB[p], pB[p]); pB[p] += BK; }
        CP_COMMIT();
        st_load += STG_BYTES;
    }

    uint32_t st_cmp = sbase;
    for (int kc = 0; kc < nch; kc++) {
        CP_WAIT1();
        __syncthreads();
        if (kc + 2 < nch) {
            #pragma unroll
            for (int p = 0; p < 4; p++) { cp16(st_load + dA[p], pA[p]); pA[p] += BK; }
            #pragma unroll
            for (int p = 0; p < 4; p++) { cp16(st_load + dB[p], pB[p]); pB[p] += BK; }
        }
        CP_COMMIT();
        st_load += STG_BYTES;
        if (st_load == sbase + NSTG * STG_BYTES) st_load = sbase;

        const uint32_t sA = st_cmp;
        const uint32_t sB = st_cmp + 16384;
        #pragma unroll
        for (int k4 = 0; k4 < 4; k4++) {
            uint32_t a[4][4];
            #pragma unroll
            for (int mi = 0; mi < 4; mi++)
                ldmx4(sA + swz(a_rb + mi * 16, k4 * 2 + a_gs),
                      a[mi][0], a[mi][1], a[mi][2], a[mi][3]);
            #pragma unroll
            for (int npp = 0; npp < 2; npp++) {
                uint32_t b0, b1, b2, b3;
                ldmx4(sB + swz(b_rb + npp * 16, k4 * 2 + b_gs), b0, b1, b2, b3);
                #pragma unroll
                for (int mi = 0; mi < 4; mi++) {
                    mma16816(acc[mi][npp*2][0], acc[mi][npp*2][1], acc[mi][npp*2][2], acc[mi][npp*2][3],
                             a[mi][0], a[mi][1], a[mi][2], a[mi][3], b0, b1);
                    mma16816(acc[mi][npp*2+1][0], acc[mi][npp*2+1][1], acc[mi][npp*2+1][2], acc[mi][npp*2+1][3],
                             a[mi][0], a[mi][1], a[mi][2], a[mi][3], b2, b3);
                }
            }
        }
        st_cmp += STG_BYTES;
        if (st_cmp == sbase + NSTG * STG_BYTES) st_cmp = sbase;
    }

    // epilogue
    const int row_in = lane >> 2;
    const int col_in = (lane & 3) * 2;

    int gi0[4], gi1[4];
    const float* pfz = g_pf2u + (size_t)z * N_ * DLAT;
    if (mode == 2) {
        const int* m2 = g_match2 + (size_t)z * (P_ * T_);
        #pragma unroll
        for (int mi = 0; mi < 4; mi++) {
            const int r0 = m0 + wm * 64 + mi * 16 + row_in;
            gi0[mi] = __ldg(m2 + r0);
            gi1[mi] = __ldg(m2 + r0 + 8);
        }
    }

    #pragma unroll
    for (int np = 0; np < 4; np++) {
        const int col = n0 + wn * 32 + np * 8 + col_in;
        float bx = 0.0f, by = 0.0f;
        if (mode != 1) { bx = __ldg(bias + col); by = __ldg(bias + col + 1); }
        #pragma unroll
        for (int mi = 0; mi < 4; mi++) {
            const int r0 = m0 + wm * 64 + mi * 16 + row_in;
            float2 c0 = make_float2(acc[mi][np][0] + bx, acc[mi][np][1] + by);
            float2 c1 = make_float2(acc[mi][np][2] + bx, acc[mi][np][3] + by);
            if (mode == 2) {
                float2 p0 = *(const float2*)(pfz + (size_t)gi0[mi] * DLAT + col);
                float2 p1 = *(const float2*)(pfz + (size_t)gi1[mi] * DLAT + col);
                c0.x += p0.x; c0.y += p0.y;
                c1.x += p1.x; c1.y += p1.y;
            }
            *(float2*)(C + (size_t)r0 * DLAT + col) = c0;
            *(float2*)(C + (size_t)(r0 + 8) * DLAT + col) = c1;
        }
    }
}

// ---------------- launch (round-15 schedule) ----------------
extern "C" void kernel_launch(void* const* d_in, const int* in_sizes, int n_in,
                              void* d_out, int out_size) {
    const float* object_surface = (const float*)d_in[0];
    const float* pre_pts        = (const float*)d_in[1];
    const float* pre_feats      = (const float*)d_in[2];
    const float* geo_raw        = (const float*)d_in[3];
    const float* obj_raw        = (const float*)d_in[4];
    const float* local_pc       = (const float*)d_in[5];
    const float* global_pc      = (const float*)d_in[6];
    const float* Wg             = (const float*)d_in[7];
    const float* bg             = (const float*)d_in[8];
    const float* Wo             = (const float*)d_in[9];
    const float* bo             = (const float*)d_in[10];
    float* out = (float*)d_out;

    static cudaStream_t s2 = nullptr;
    static cudaEvent_t evFork = nullptr, evNN = nullptr, evMatch = nullptr;
    static bool inited = false;
    if (!inited) {
        cudaFuncSetAttribute(gemm_mma, cudaFuncAttributeMaxDynamicSharedMemorySize, GEMM_SMEM);
        cudaStreamCreateWithFlags(&s2, cudaStreamNonBlocking);
        cudaEventCreateWithFlags(&evFork, cudaEventDisableTiming);
        cudaEventCreateWithFlags(&evNN, cudaEventDisableTiming);
        cudaEventCreateWithFlags(&evMatch, cudaEventDisableTiming);
        inited = true;
    }

    __half* gA  = nullptr; cudaGetSymbolAddress((void**)&gA,  g_A);
    __half* gPF = nullptr; cudaGetSymbolAddress((void**)&gPF, g_PF);
    __half* gB1 = nullptr; cudaGetSymbolAddress((void**)&gB1, g_B1);
    __half* gB2 = nullptr; cudaGetSymbolAddress((void**)&gB2, g_B2);
    float* gPU  = nullptr; cudaGetSymbolAddress((void**)&gPU, g_pf2u);

    // fork: NN chain on s2
    cudaEventRecord(evFork, 0);
    cudaStreamWaitEvent(s2, evFork, 0);

    nn1_partial<<<dim3(N_ / 1024, MSPLIT), 256, 0, s2>>>(object_surface, pre_pts);
    cudaEventRecord(evNN, s2);
    match_partial<<<dim3(T_ / 1024, P_, 2 * NSCH), 256, 0, s2>>>(object_surface, local_pc, global_pc);
    match_reduce<<<2 * P_ * T_ / 256, 256, 0, s2>>>();
    cudaEventRecord(evMatch, s2);

    // main stream: fused prep, then pf2u chain (after nn1), then big GEMM
    prep<<<2 * P_ * T_ + 2 * 1536, 256>>>(geo_raw, obj_raw, Wg, Wo);

    cudaStreamWaitEvent(0, evNN, 0);
    reduce_gatherPF<<<N_, DFEAT / 4>>>(pre_feats);
    gemm_mma<<<dim3(DLAT / BN, N_ / BM, 2), 256, GEMM_SMEM>>>(
        gPF, gB2, gPU, nullptr, nullptr,
        DFEAT, DFEAT / BK, 0, (size_t)DLAT * DFEAT, (size_t)N_ * DLAT, 1);

    cudaStreamWaitEvent(0, evMatch, 0);
    gemm_mma<<<dim3(DLAT / BN, (P_ * T_) / BM, 2), 256, GEMM_SMEM>>>(
        gA, gB1, out, bg, bo,
        DLAT, DLAT / BK, (size_t)(P_ * T_) * DLAT, (size_t)DLAT * DLAT,
        (size_t)(P_ * T_) * DLAT, 2);
}

// round 17
// speedup vs baseline: 1.1715x; 1.0426x over previous
#include <cuda_runtime.h>
#include <cuda_fp16.h>
#include <cstdint>

#define P_    8
#define T_    2048
#define N_    8192
#define M_    20000
#define DLAT  1024
#define DFEAT 512
#define DIN   1536
#define MSPLIT 20
#define MCHUNK 1000

// ---- GEMM config ----
#define BM 128
#define BN 128
#define BK 64
#define NSTG 3
#define STG_BYTES 32768
#define GEMM_SMEM (NSTG * STG_BYTES)   // 96KB

// ---------------- scratch ----------------
__device__ float g_part_d[N_ * MSPLIT];
__device__ int   g_part_i[N_ * MSPLIT];
__device__ int   g_match2[2 * P_ * T_];                    // [which][p][t] -> obj idx
__device__ __half g_A[2L * P_ * T_ * DLAT];
__device__ __half g_PF[(size_t)N_ * DFEAT];
__device__ __half g_B1[2L * DLAT * DLAT];
__device__ __half g_B2[2L * DLAT * DFEAT];
__device__ float g_pf2u[2L * N_ * DLAT];
__device__ __align__(16) __half g_MB[(size_t)P_ * N_ * 16];  // cand table, 2MB

// ---------------- helpers ----------------
__device__ __forceinline__ uint32_t smem_u32(const void* p) {
    uint32_t a;
    asm("{ .reg .u64 t; cvta.to.shared.u64 t, %1; cvt.u32.u64 %0, t; }" : "=r"(a) : "l"(p));
    return a;
}
__device__ __forceinline__ void cp16(uint32_t dst, const void* src) {
    asm volatile("cp.async.cg.shared.global [%0], [%1], 16;" :: "r"(dst), "l"(src) : "memory");
}
#define CP_COMMIT() asm volatile("cp.async.commit_group;" ::: "memory")
#define CP_WAIT1()  asm volatile("cp.async.wait_group 1;" ::: "memory")

__device__ __forceinline__ void ldmx4(uint32_t addr, uint32_t& r0, uint32_t& r1,
                                      uint32_t& r2, uint32_t& r3) {
    asm volatile("ldmatrix.sync.aligned.m8n8.x4.shared.b16 {%0,%1,%2,%3}, [%4];"
                 : "=r"(r0), "=r"(r1), "=r"(r2), "=r"(r3) : "r"(addr));
}
__device__ __forceinline__ void mma16816(float& c0, float& c1, float& c2, float& c3,
                                         uint32_t a0, uint32_t a1, uint32_t a2, uint32_t a3,
                                         uint32_t b0, uint32_t b1) {
    asm volatile("mma.sync.aligned.m16n8k16.row.col.f32.f16.f16.f32 "
                 "{%0,%1,%2,%3}, {%4,%5,%6,%7}, {%8,%9}, {%0,%1,%2,%3};"
                 : "+f"(c0), "+f"(c1), "+f"(c2), "+f"(c3)
                 : "r"(a0), "r"(a1), "r"(a2), "r"(a3), "r"(b0), "r"(b1));
}
__device__ __forceinline__ uint32_t swz(int row, int kg) {
    return (uint32_t)(row * 128 + ((kg ^ (row & 7)) << 4));
}
// swizzle for 32B-row tiles (match kernel): granule g XOR bit2 of row
__device__ __forceinline__ uint32_t swz32(int row, int g) {
    return (uint32_t)(row * 32 + ((g ^ ((row >> 2) & 1)) << 4));
}
__device__ __forceinline__ uint2 pack4h(float4 v) {
    __half hx = __float2half_rn(v.x), hy = __float2half_rn(v.y);
    __half hz = __float2half_rn(v.z), hw = __float2half_rn(v.w);
    uint2 r;
    r.x = ((uint32_t)*(uint16_t*)&hy << 16) | (uint32_t)*(uint16_t*)&hx;
    r.y = ((uint32_t)*(uint16_t*)&hw << 16) | (uint32_t)*(uint16_t*)&hz;
    return r;
}
__device__ __forceinline__ void split_h(float v, __half& h, __half& l) {
    h = __float2half_rn(v);
    l = __float2half_rn(v - __half2float(h));
}

// ---------------- kernel 1: nn1 (scalar, proven) ----------------
__global__ void nn1_partial(const float* __restrict__ os, const float* __restrict__ pts) {
    __shared__ float4 sP[MCHUNK];
    const int ms = blockIdx.y;
    const int m0 = ms * MCHUNK;
    for (int i = threadIdx.x; i < MCHUNK; i += 256) {
        float x = pts[(size_t)(m0 + i) * 3 + 0];
        float y = pts[(size_t)(m0 + i) * 3 + 1];
        float z = pts[(size_t)(m0 + i) * 3 + 2];
        sP[i] = make_float4(x, y, z, x * x + y * y + z * z);
    }
    __syncthreads();
    float qx[4], qy[4], qz[4], best[4];
    int bi[4];
    #pragma unroll
    for (int u = 0; u < 4; u++) {
        const int q = blockIdx.x * 1024 + u * 256 + threadIdx.x;
        qx[u] = -2.0f * os[(size_t)q * 6 + 0];
        qy[u] = -2.0f * os[(size_t)q * 6 + 1];
        qz[u] = -2.0f * os[(size_t)q * 6 + 2];
        best[u] = 3.4e38f;
        bi[u] = 0;
    }
    #pragma unroll 4
    for (int i = 0; i < MCHUNK; i++) {
        float4 c = sP[i];
        #pragma unroll
        for (int u = 0; u < 4; u++) {
            float d = fmaf(qx[u], c.x, fmaf(qy[u], c.y, fmaf(qz[u], c.z, c.w)));
            if (d < best[u]) { best[u] = d; bi[u] = i; }
        }
    }
    #pragma unroll
    for (int u = 0; u < 4; u++) {
        const int q = blockIdx.x * 1024 + u * 256 + threadIdx.x;
        g_part_d[q * MSPLIT + ms] = best[u];
        g_part_i[q * MSPLIT + ms] = m0 + bi[u];
    }
}

// fused nn1_reduce + gatherPF
__global__ void reduce_gatherPF(const float* __restrict__ pf) {
    const int q = blockIdx.x;
    float best = g_part_d[q * MSPLIT];
    int bi = g_part_i[q * MSPLIT];
    #pragma unroll
    for (int s = 1; s < MSPLIT; s++) {
        float d = g_part_d[q * MSPLIT + s];
        if (d < best) { best = d; bi = g_part_i[q * MSPLIT + s]; }
    }
    float4 v = *(const float4*)(pf + (size_t)bi * DFEAT + threadIdx.x * 4);
    *(uint2*)(g_PF + (size_t)q * DFEAT + threadIdx.x * 4) = pack4h(v);
}

// ---------------- candprep: obj pts -> fp16 hi/lo MMA table ----------------
// grid 256, block 256: idx = p*8192 + c
__global__ void candprep(const float* __restrict__ os) {
    const int idx = blockIdx.x * 256 + threadIdx.x;
    const int p = idx >> 13;
    const int c = idx & (N_ - 1);
    const size_t b = ((size_t)p * N_ + c) * 6;
    float x = os[b + 0], y = os[b + 1], z = os[b + 2];
    float c2 = fmaf(x, x, fmaf(y, y, z * z));
    __half xh, xl, yh, yl, zh, zl, c2h, c2l;
    split_h(x, xh, xl); split_h(y, yh, yl); split_h(z, zh, zl); split_h(c2, c2h, c2l);
    __half h[16];
    h[0] = xh; h[1] = xl; h[2] = xh;
    h[3] = yh; h[4] = yl; h[5] = yh;
    h[6] = zh; h[7] = zl; h[8] = zh;
    h[9] = c2h; h[10] = c2l;
    h[11] = __ushort_as_half(0); h[12] = h[11]; h[13] = h[11]; h[14] = h[11]; h[15] = h[11];
    uint4* dst = (uint4*)(g_MB + (size_t)idx * 16);
    dst[0] = *(uint4*)&h[0];
    dst[1] = *(uint4*)&h[8];
}

// ---------------- match via MMA + fused argmin ----------------
// grid (T/128, P, 2), block 256 (8 warps x 16 queries)
__global__ void __launch_bounds__(256) match_mma(
    const float* __restrict__ local_pc, const float* __restrict__ global_pc) {
    __shared__ __align__(16) __half sA[128 * 16];       // 4KB
    __shared__ __align__(16) __half sB[2][128 * 16];    // 2 x 4KB
    const int p = blockIdx.y;
    const int which = blockIdx.z;
    const int qbase = blockIdx.x * 128;
    const int tid = threadIdx.x;
    const int wid = tid >> 5;
    const int lane = tid & 31;
    const float* qsrc = which ? global_pc : local_pc;

    // build A rows (query side: -2*hi/lo, 1, 1)
    if (tid < 128) {
        const size_t qb = ((size_t)p * T_ + qbase + tid) * 3;
        float qx = qsrc[qb + 0], qy = qsrc[qb + 1], qz = qsrc[qb + 2];
        __half xh, xl, yh, yl, zh, zl;
        split_h(qx, xh, xl); split_h(qy, yh, yl); split_h(qz, zh, zl);
        __half axh = __float2half_rn(-2.0f * __half2float(xh));
        __half axl = __float2half_rn(-2.0f * __half2float(xl));
        __half ayh = __float2half_rn(-2.0f * __half2float(yh));
        __half ayl = __float2half_rn(-2.0f * __half2float(yl));
        __half azh = __float2half_rn(-2.0f * __half2float(zh));
        __half azl = __float2half_rn(-2.0f * __half2float(zl));
        __half one = __float2half_rn(1.0f);
        __half zero = __ushort_as_half(0);
        __half h[16];
        h[0] = axh; h[1] = axh; h[2] = axl;
        h[3] = ayh; h[4] = ayh; h[5] = ayl;
        h[6] = azh; h[7] = azh; h[8] = azl;
        h[9] = one; h[10] = one;
        h[11] = zero; h[12] = zero; h[13] = zero; h[14] = zero; h[15] = zero;
        char* base = (char*)sA;
        *(uint4*)(base + swz32(tid, 0)) = *(uint4*)&h[0];
        *(uint4*)(base + swz32(tid, 1)) = *(uint4*)&h[8];
    }
    __syncthreads();

    // A fragment (held all kernel): rows wid*16 + (lane&15), granule lane>>4
    uint32_t a0, a1, a2, a3;
    {
        const int r = wid * 16 + (lane & 15);
        const int g = lane >> 4;
        ldmx4(smem_u32(sA) + swz32(r, g), a0, a1, a2, a3);
    }

    const uint32_t sb0 = smem_u32(&sB[0][0]);
    const uint32_t sb1 = smem_u32(&sB[1][0]);
    const int lrow = tid >> 1;          // cand row for loader
    const int lg = tid & 1;
    const __half* msrc = g_MB + ((size_t)p * N_ + lrow) * 16 + lg * 8;
    const uint32_t ldst = swz32(lrow, lg);

    float best0 = 3.4e38f, best1 = 3.4e38f;
    int bi0 = 0, bi1 = 0;
    const int b_r = (lane & 7) + ((lane & 16) >> 1);
    const int b_g = (lane >> 3) & 1;
    const int col_in = (lane & 3) * 2;

    // prologue: tile 0
    cp16(sb0 + ldst, msrc);
    CP_COMMIT();

    const int NIT = N_ / 128;   // 64
    for (int it = 0; it < NIT; it++) {
        if (it + 1 < NIT)
            cp16(((it + 1) & 1 ? sb1 : sb0) + ldst, msrc + (size_t)(it + 1) * 128 * 16);
        CP_COMMIT();
        CP_WAIT1();
        __syncthreads();

        const uint32_t sb = (it & 1) ? sb1 : sb0;
        const int c0 = it * 128;
        #pragma unroll
        for (int np2 = 0; np2 < 8; np2++) {
            uint32_t b0, b1, b2, b3;
            const int rr = np2 * 16 + b_r;
            ldmx4(sb + swz32(rr, b_g), b0, b1, b2, b3);
            {
                float d0 = 0.f, d1 = 0.f, d2 = 0.f, d3 = 0.f;
                mma16816(d0, d1, d2, d3, a0, a1, a2, a3, b0, b1);
                const int cb = c0 + np2 * 16 + col_in;
                if (d0 < best0) { best0 = d0; bi0 = cb; }
                if (d1 < best0) { best0 = d1; bi0 = cb + 1; }
                if (d2 < best1) { best1 = d2; bi1 = cb; }
                if (d3 < best1) { best1 = d3; bi1 = cb + 1; }
            }
            {
                float d0 = 0.f, d1 = 0.f, d2 = 0.f, d3 = 0.f;
                mma16816(d0, d1, d2, d3, a0, a1, a2, a3, b2, b3);
                const int cb = c0 + np2 * 16 + 8 + col_in;
                if (d0 < best0) { best0 = d0; bi0 = cb; }
                if (d1 < best0) { best0 = d1; bi0 = cb + 1; }
                if (d2 < best1) { best1 = d2; bi1 = cb; }
                if (d3 < best1) { best1 = d3; bi1 = cb + 1; }
            }
        }
        __syncthreads();
    }

    // quad merge (lanes sharing a row differ in lane&3); tie -> lower index
    #pragma unroll
    for (int m = 1; m < 4; m <<= 1) {
        float ob = __shfl_xor_sync(0xFFFFFFFFu, best0, m);
        int oi = __shfl_xor_sync(0xFFFFFFFFu, bi0, m);
        if (ob < best0 || (ob == best0 && oi < bi0)) { best0 = ob; bi0 = oi; }
        ob = __shfl_xor_sync(0xFFFFFFFFu, best1, m);
        oi = __shfl_xor_sync(0xFFFFFFFFu, bi1, m);
        if (ob < best1 || (ob == best1 && oi < bi1)) { best1 = ob; bi1 = oi; }
    }
    if ((lane & 3) == 0) {
        const int q = qbase + wid * 16 + (lane >> 2);
        int* m2 = g_match2 + (size_t)which * (P_ * T_) + (size_t)p * T_;
        m2[q] = bi0;
        m2[q + 8] = bi1;
    }
}

// ---------------- fused prep: convA + convW ----------------
__global__ void prep(const float* __restrict__ geo_raw, const float* __restrict__ obj_raw,
                     const float* __restrict__ Wg, const float* __restrict__ Wo) {
    __shared__ float tile[32][33];
    const int bid = blockIdx.x;
    if (bid < 2 * P_ * T_) {
        const int z = bid >> 14;
        const int m = bid & 16383;
        const float* src = (z ? obj_raw : geo_raw) + (size_t)m * DLAT + threadIdx.x * 4;
        float4 v = *(const float4*)src;
        size_t base = ((size_t)z * (P_ * T_) + m) * DLAT + threadIdx.x * 4;
        *(uint2*)(g_A + base) = pack4h(v);
    } else {
        const int idx = bid - 2 * P_ * T_;
        const int g = idx / 1536;
        const int rem = idx % 1536;
        const int kb = (rem % 48) * 32;
        const int nb = (rem / 48) * 32;
        const float* W = g ? Wo : Wg;
        const int tx = threadIdx.x & 31;
        const int ty = threadIdx.x >> 5;
        for (int i = ty; i < 32; i += 8)
            tile[i][tx] = W[(size_t)(kb + i) * DLAT + nb + tx];
        __syncthreads();
        const int k = kb + tx;
        for (int i = ty; i < 32; i += 8) {
            __half h = __float2half_rn(tile[tx][i]);
            const int n = nb + i;
            if (k < DLAT)
                g_B1[(size_t)g * DLAT * DLAT + (size_t)n * DLAT + k] = h;
            else
                g_B2[(size_t)g * DLAT * DFEAT + (size_t)n * DFEAT + (k - DLAT)] = h;
        }
    }
}

// ---------------- GEMM (round-16 strength-reduced loader) ----------------
extern __shared__ char dynsmem[];

__global__ void __launch_bounds__(256, 2)
gemm_mma(const __half* __restrict__ Abase, const __half* __restrict__ Bbase,
         float* __restrict__ Cbase,
         const float* __restrict__ bg, const float* __restrict__ bo,
         int kdim, int nch,
         size_t strideAz, size_t strideBz, size_t strideCz, int mode) {
    const int z = blockIdx.z;
    const int n0 = blockIdx.x * BN;
    const int m0 = blockIdx.y * BM;
    const int tid = threadIdx.x;
    const int wid = tid >> 5;
    const int lane = tid & 31;
    const int wm = wid & 1;
    const int wn = wid >> 1;

    float* C = Cbase + (size_t)z * strideCz;
    const float* bias = z ? bo : bg;

    const uint32_t sbase = smem_u32(dynsmem);

    const int lrow = tid >> 3;
    const int lkg = tid & 7;
    const __half* pA[4];
    const __half* pB[4];
    uint32_t dA[4], dB[4];
    {
        const __half* A = Abase + (size_t)z * strideAz;
        const __half* B = Bbase + (size_t)z * strideBz;
        #pragma unroll
        for (int p = 0; p < 4; p++) {
            const int rw = lrow + p * 32;
            pA[p] = A + (size_t)(m0 + rw) * kdim + lkg * 8;
            pB[p] = B + (size_t)(n0 + rw) * kdim + lkg * 8;
            dA[p] = swz(rw, lkg);
            dB[p] = 16384u + swz(rw, lkg);
        }
    }

    float acc[4][4][4];
    #pragma unroll
    for (int i = 0; i < 4; i++)
        #pragma unroll
        for (int j = 0; j < 4; j++)
            #pragma unroll
            for (int r = 0; r < 4; r++) acc[i][j][r] = 0.0f;

    const int a_rb = wm * 64 + (lane & 15);
    const int a_gs = lane >> 4;
    const int b_rb = wn * 32 + (lane & 7) + ((lane & 16) >> 1);
    const int b_gs = (lane >> 3) & 1;

    uint32_t st_load = sbase;
    #pragma unroll
    for (int s = 0; s < 2; s++) {
        #pragma unroll
        for (int p = 0; p < 4; p++) { cp16(st_load + dA[p], pA[p]); pA[p] += BK; }
        #pragma unroll
        for (int p = 0; p < 4; p++) { cp16(st_load + dB[p], pB[p]); pB[p] += BK; }
        CP_COMMIT();
        st_load += STG_BYTES;
    }

    uint32_t st_cmp = sbase;
    for (int kc = 0; kc < nch; kc++) {
        CP_WAIT1();
        __syncthreads();
        if (kc + 2 < nch) {
            #pragma unroll
            for (int p = 0; p < 4; p++) { cp16(st_load + dA[p], pA[p]); pA[p] += BK; }
            #pragma unroll
            for (int p = 0; p < 4; p++) { cp16(st_load + dB[p], pB[p]); pB[p] += BK; }
        }
        CP_COMMIT();
        st_load += STG_BYTES;
        if (st_load == sbase + NSTG * STG_BYTES) st_load = sbase;

        const uint32_t sA = st_cmp;
        const uint32_t sB = st_cmp + 16384;
        #pragma unroll
        for (int k4 = 0; k4 < 4; k4++) {
            uint32_t a[4][4];
            #pragma unroll
            for (int mi = 0; mi < 4; mi++)
                ldmx4(sA + swz(a_rb + mi * 16, k4 * 2 + a_gs),
                      a[mi][0], a[mi][1], a[mi][2], a[mi][3]);
            #pragma unroll
            for (int npp = 0; npp < 2; npp++) {
                uint32_t b0, b1, b2, b3;
                ldmx4(sB + swz(b_rb + npp * 16, k4 * 2 + b_gs), b0, b1, b2, b3);
                #pragma unroll
                for (int mi = 0; mi < 4; mi++) {
                    mma16816(acc[mi][npp*2][0], acc[mi][npp*2][1], acc[mi][npp*2][2], acc[mi][npp*2][3],
                             a[mi][0], a[mi][1], a[mi][2], a[mi][3], b0, b1);
                    mma16816(acc[mi][npp*2+1][0], acc[mi][npp*2+1][1], acc[mi][npp*2+1][2], acc[mi][npp*2+1][3],
                             a[mi][0], a[mi][1], a[mi][2], a[mi][3], b2, b3);
                }
            }
        }
        st_cmp += STG_BYTES;
        if (st_cmp == sbase + NSTG * STG_BYTES) st_cmp = sbase;
    }

    const int row_in = lane >> 2;
    const int col_in = (lane & 3) * 2;

    int gi0[4], gi1[4];
    const float* pfz = g_pf2u + (size_t)z * N_ * DLAT;
    if (mode == 2) {
        const int* m2 = g_match2 + (size_t)z * (P_ * T_);
        #pragma unroll
        for (int mi = 0; mi < 4; mi++) {
            const int r0 = m0 + wm * 64 + mi * 16 + row_in;
            gi0[mi] = __ldg(m2 + r0);
            gi1[mi] = __ldg(m2 + r0 + 8);
        }
    }

    #pragma unroll
    for (int np = 0; np < 4; np++) {
        const int col = n0 + wn * 32 + np * 8 + col_in;
        float bx = 0.0f, by = 0.0f;
        if (mode != 1) { bx = __ldg(bias + col); by = __ldg(bias + col + 1); }
        #pragma unroll
        for (int mi = 0; mi < 4; mi++) {
            const int r0 = m0 + wm * 64 + mi * 16 + row_in;
            float2 c0 = make_float2(acc[mi][np][0] + bx, acc[mi][np][1] + by);
            float2 c1 = make_float2(acc[mi][np][2] + bx, acc[mi][np][3] + by);
            if (mode == 2) {
                float2 p0 = *(const float2*)(pfz + (size_t)gi0[mi] * DLAT + col);
                float2 p1 = *(const float2*)(pfz + (size_t)gi1[mi] * DLAT + col);
                c0.x += p0.x; c0.y += p0.y;
                c1.x += p1.x; c1.y += p1.y;
            }
            *(float2*)(C + (size_t)r0 * DLAT + col) = c0;
            *(float2*)(C + (size_t)(r0 + 8) * DLAT + col) = c1;
        }
    }
}

// ---------------- launch ----------------
extern "C" void kernel_launch(void* const* d_in, const int* in_sizes, int n_in,
                              void* d_out, int out_size) {
    const float* object_surface = (const float*)d_in[0];
    const float* pre_pts        = (const float*)d_in[1];
    const float* pre_feats      = (const float*)d_in[2];
    const float* geo_raw        = (const float*)d_in[3];
    const float* obj_raw        = (const float*)d_in[4];
    const float* local_pc       = (const float*)d_in[5];
    const float* global_pc      = (const float*)d_in[6];
    const float* Wg             = (const float*)d_in[7];
    const float* bg             = (const float*)d_in[8];
    const float* Wo             = (const float*)d_in[9];
    const float* bo             = (const float*)d_in[10];
    float* out = (float*)d_out;

    static cudaStream_t s2 = nullptr;
    static cudaEvent_t evFork = nullptr, evNN = nullptr, evMatch = nullptr;
    static bool inited = false;
    if (!inited) {
        cudaFuncSetAttribute(gemm_mma, cudaFuncAttributeMaxDynamicSharedMemorySize, GEMM_SMEM);
        cudaStreamCreateWithFlags(&s2, cudaStreamNonBlocking);
        cudaEventCreateWithFlags(&evFork, cudaEventDisableTiming);
        cudaEventCreateWithFlags(&evNN, cudaEventDisableTiming);
        cudaEventCreateWithFlags(&evMatch, cudaEventDisableTiming);
        inited = true;
    }

    __half* gA  = nullptr; cudaGetSymbolAddress((void**)&gA,  g_A);
    __half* gPF = nullptr; cudaGetSymbolAddress((void**)&gPF, g_PF);
    __half* gB1 = nullptr; cudaGetSymbolAddress((void**)&gB1, g_B1);
    __half* gB2 = nullptr; cudaGetSymbolAddress((void**)&gB2, g_B2);
    float* gPU  = nullptr; cudaGetSymbolAddress((void**)&gPU, g_pf2u);

    // fork: NN chain on s2
    cudaEventRecord(evFork, 0);
    cudaStreamWaitEvent(s2, evFork, 0);

    candprep<<<P_ * N_ / 256, 256, 0, s2>>>(object_surface);
    nn1_partial<<<dim3(N_ / 1024, MSPLIT), 256, 0, s2>>>(object_surface, pre_pts);
    cudaEventRecord(evNN, s2);
    match_mma<<<dim3(T_ / 128, P_, 2), 256, 0, s2>>>(local_pc, global_pc);
    cudaEventRecord(evMatch, s2);

    // main stream: fused prep, then pf2u chain (after nn1), then big GEMM
    prep<<<2 * P_ * T_ + 2 * 1536, 256>>>(geo_raw, obj_raw, Wg, Wo);

    cudaStreamWaitEvent(0, evNN, 0);
    reduce_gatherPF<<<N_, DFEAT / 4>>>(pre_feats);
    gemm_mma<<<dim3(DLAT / BN, N_ / BM, 2), 256, GEMM_SMEM>>>(
        gPF, gB2, gPU, nullptr, nullptr,
        DFEAT, DFEAT / BK, 0, (size_t)DLAT * DFEAT, (size_t)N_ * DLAT, 1);

    cudaStreamWaitEvent(0, evMatch, 0);
    gemm_mma<<<dim3(DLAT / BN, (P_ * T_) / BM, 2), 256, GEMM_SMEM>>>(
        gA, gB1, out, bg, bo,
        DLAT, DLAT / BK, (size_t)(P_ * T_) * DLAT, (size_t)DLAT * DLAT,
        (size_t)(P_ * T_) * DLAT, 2);
}